// round 8
// baseline (speedup 1.0000x reference)
#include <cuda_runtime.h>
#include <math.h>

// Problem constants (fixed by setup_inputs)
#define Bc 2
#define Vc 50000
#define Tc 3
#define Nc 32
#define Fc 128
#define Uc 128
#define Ec 300000
#define NV (Bc*Vc)          // 100000 vertices
#define SLOTS (Tc*Nc)       // 96 slots per vertex

typedef unsigned long long ull;

// Scratch (device globals; no allocation allowed)
__device__ float g_logits[Tc*Ec];
__device__ int   g_winner[NV*SLOTS];
__device__ float g_m[NV];
__device__ float g_c[NV];
__device__ float g_fdot[NV];
__device__ float g_wtilde[Tc*Fc];   // W_t @ W_att[128:]
__device__ float g_cterm[Tc];       // b_t · W_att[128:]

// ---------------------------------------------------------------------------
// K0: init winner grid to -1, out to 0 (vectorized)
// ---------------------------------------------------------------------------
__global__ void init_kernel(float4* __restrict__ out) {
    int i = blockIdx.x * 256 + threadIdx.x;
    if (i < NV*Uc/4)    out[i] = make_float4(0.f, 0.f, 0.f, 0.f);
    if (i < NV*SLOTS/4) ((int4*)g_winner)[i] = make_int4(-1, -1, -1, -1);
}

// ---------------------------------------------------------------------------
// K1: fdot[bv] = features[bv]·W_att[0:128] + b_att   (one warp per vertex)
// ---------------------------------------------------------------------------
__global__ void fdot_kernel(const float* __restrict__ feat,
                            const float* __restrict__ Wa,
                            const float* __restrict__ ba) {
    int w = (blockIdx.x * blockDim.x + threadIdx.x) >> 5;
    int lane = threadIdx.x & 31;
    if (w >= NV) return;
    const float4 f = ((const float4*)(feat + (size_t)w * Fc))[lane];
    const float4 a = __ldg(((const float4*)Wa) + lane);
    float s = f.x*a.x + f.y*a.y + f.z*a.z + f.w*a.w;
#pragma unroll
    for (int o = 16; o; o >>= 1)
        s += __shfl_xor_sync(0xffffffffu, s, o);
    if (lane == 0) g_fdot[w] = s + ba[0];
}

// ---------------------------------------------------------------------------
// K1b: w̃_t[f] = sum_u W_t[f,u]*Wa2[u],  cterm[t] = sum_u b_t[u]*Wa2[u]
// ---------------------------------------------------------------------------
__global__ void prep_kernel(const float* __restrict__ Wd,
                            const float* __restrict__ bd,
                            const float* __restrict__ Wa) {
    int t = blockIdx.x;
    int f = threadIdx.x;   // 128
    const float* row = Wd + ((size_t)t * 128 + f) * 128;
    float s = 0.f;
#pragma unroll 8
    for (int u = 0; u < 128; u++) s += row[u] * __ldg(&Wa[128 + u]);
    g_wtilde[t * 128 + f] = s;
    if (f == 0) {
        float cb = 0.f;
        for (int u = 0; u < 128; u++) cb += bd[t * 128 + u] * Wa[128 + u];
        g_cterm[t] = cb;
    }
}

// ---------------------------------------------------------------------------
// K2: logits via matrix-vector: logit = leaky(fdot[bv] + ef·w̃_t + cterm_t)
//     + last-write-wins winner scatter (atomicMax on edge id).
//     One warp per edge; memory bound on ef (460 MB).
// ---------------------------------------------------------------------------
__global__ void logits_kernel(const float* __restrict__ ef,
                              const int*   __restrict__ eidx) {
    int wg = (blockIdx.x * 256 + threadIdx.x) >> 5;
    int lane = threadIdx.x & 31;
    if (wg >= Tc * Ec) return;
    int t = wg / Ec;
    int e = wg - t * Ec;
    const float4 a = ((const float4*)(ef + ((size_t)t * Ec + e) * 128))[lane];
    const float4 w = __ldg(((const float4*)(g_wtilde + t * 128)) + lane);
    float s = a.x*w.x + a.y*w.y + a.z*w.z + a.w*w.w;
#pragma unroll
    for (int o = 16; o; o >>= 1)
        s += __shfl_xor_sync(0xffffffffu, s, o);
    if (lane == 0) {
        const int* ei = eidx + ((size_t)t * Ec + e) * 3;
        int b = ei[0], v = ei[1], sl = ei[2];
        int bv = b * Vc + v;
        float x = g_fdot[bv] + s + g_cterm[t];
        float logit = (x > 0.0f) ? x : 0.3f * x;
        g_logits[t * Ec + e] = logit;
        atomicMax(&g_winner[bv * SLOTS + t * Nc + sl], e);
    }
}

// ---------------------------------------------------------------------------
// K3: per-vertex softmax stats: m, c = degree/den.   One warp per vertex.
// ---------------------------------------------------------------------------
__global__ void vertex_kernel(const int* __restrict__ adj) {
    int vert = (blockIdx.x * blockDim.x + threadIdx.x) >> 5;
    int lane = threadIdx.x & 31;
    if (vert >= NV) return;
    const int base = vert * SLOTS;

    float l[3];
    int deg = 0;
#pragma unroll
    for (int i = 0; i < 3; i++) {
        int slot = i * 32 + lane;
        int w = g_winner[base + slot];
        deg += (adj[base + slot] >= 0) ? 1 : 0;
        l[i] = (w >= 0) ? g_logits[i * Ec + w] : -200.0f;
    }
    float m = fmaxf(fmaxf(l[0], l[1]), l[2]);
#pragma unroll
    for (int o = 16; o; o >>= 1)
        m = fmaxf(m, __shfl_xor_sync(0xffffffffu, m, o));
    float den = expf(l[0] - m) + expf(l[1] - m) + expf(l[2] - m);
#pragma unroll
    for (int o = 16; o; o >>= 1) {
        den += __shfl_xor_sync(0xffffffffu, den, o);
        deg += __shfl_xor_sync(0xffffffffu, deg, o);
    }
    if (lane == 0) {
        g_m[vert] = m;
        g_c[vert] = (float)deg / den;
    }
}

// ---------------------------------------------------------------------------
// K4: fused GEMM + weighted scatter.
//     xform = A @ W + b computed in registers (128x128 tile, 8x8 microtile,
//     packed f32x2 FMA); epilogue multiplies each row by att(e) and
//     atomic-adds float4s directly into out[bv]. No xform round-trip.
// ---------------------------------------------------------------------------
__global__ __launch_bounds__(256, 2)
void gemm_scatter_kernel(const float* __restrict__ ef,    // [T,E,128]
                         const float* __restrict__ Wd,    // [T,128,128]
                         const float* __restrict__ bd,    // [T,128]
                         const int*   __restrict__ eidx,  // [T,E,3]
                         float* __restrict__ out)
{
    __shared__ float sA[16][132];   // A chunk, transposed [k][row], padded
    __shared__ float sW[16][128];   // W chunk [k][u]
    __shared__ float satt[128];
    __shared__ int   sbv[128];

    const int t  = blockIdx.y;
    const int e0 = blockIdx.x * 128;
    const int rows = min(128, Ec - e0);
    const int tid = threadIdx.x;
    const int tx = tid & 15;        // 16 col-groups of 8
    const int ty = tid >> 4;        // 16 row-groups of 8

    const float* A = ef + ((size_t)t * Ec + e0) * 128;
    const float* W = Wd + (size_t)t * 128 * 128;

    // att per row while mainloop data is being staged (winner/logits/m/c ready)
    if (tid < rows) {
        int e = e0 + tid;
        const int* ei = eidx + ((size_t)t * Ec + e) * 3;
        int b = ei[0], v = ei[1], s = ei[2];
        int bv = b * Vc + v;
        int w = g_winner[bv * SLOTS + t * Nc + s];
        satt[tid] = expf(g_logits[t * Ec + w] - g_m[bv]) * g_c[bv];
        sbv[tid]  = bv;
    }

    ull acc[8][4];
#pragma unroll
    for (int i = 0; i < 8; i++)
#pragma unroll
        for (int j = 0; j < 4; j++) acc[i][j] = 0ull;

    for (int kc = 0; kc < 8; kc++) {
        const int kb = kc * 16;
        // load A chunk (transposed into sA[k][row])
        {
            int q = tid & 3;
            int r = tid >> 2;
#pragma unroll
            for (int it = 0; it < 2; it++) {
                int row = r + 64 * it;
                float4 v = make_float4(0.f, 0.f, 0.f, 0.f);
                if (row < rows)
                    v = *(const float4*)(A + (size_t)row * 128 + kb + q * 4);
                sA[q*4+0][row] = v.x;
                sA[q*4+1][row] = v.y;
                sA[q*4+2][row] = v.z;
                sA[q*4+3][row] = v.w;
            }
        }
        // load W chunk
        {
            int c4 = tid & 31;
            int kr = tid >> 5;
#pragma unroll
            for (int it = 0; it < 2; it++) {
                int k = kr + 8 * it;
                *(float4*)&sW[k][c4*4] = *(const float4*)(W + (size_t)(kb + k) * 128 + c4 * 4);
            }
        }
        __syncthreads();
#pragma unroll
        for (int k = 0; k < 16; k++) {
            float4 a0 = *(const float4*)&sA[k][ty*8];
            float4 a1 = *(const float4*)&sA[k][ty*8 + 4];
            ull w2[4];
#pragma unroll
            for (int j = 0; j < 4; j++)
                w2[j] = *(const ull*)&sW[k][tx*8 + 2*j];
            float av[8] = {a0.x, a0.y, a0.z, a0.w, a1.x, a1.y, a1.z, a1.w};
#pragma unroll
            for (int i = 0; i < 8; i++) {
                ull ad;
                asm("mov.b64 %0, {%1, %1};" : "=l"(ad) : "f"(av[i]));
#pragma unroll
                for (int j = 0; j < 4; j++)
                    asm("fma.rn.f32x2 %0, %1, %2, %0;" : "+l"(acc[i][j]) : "l"(ad), "l"(w2[j]));
            }
        }
        __syncthreads();
    }

    // epilogue: bias, att-weight, scatter-add
    float bias[8];
#pragma unroll
    for (int j = 0; j < 8; j++) bias[j] = bd[t*128 + tx*8 + j];

#pragma unroll
    for (int i = 0; i < 8; i++) {
        int r = ty*8 + i;
        if (r >= rows) break;
        float att = satt[r];
        int bv = sbv[r];
        float cc[8];
#pragma unroll
        for (int j = 0; j < 4; j++) {
            float lo, hi;
            asm("mov.b64 {%0, %1}, %2;" : "=f"(lo), "=f"(hi) : "l"(acc[i][j]));
            cc[2*j]   = (lo + bias[2*j])   * att;
            cc[2*j+1] = (hi + bias[2*j+1]) * att;
        }
        float4* dst = (float4*)(out + (size_t)bv * 128 + tx*8);
        atomicAdd(dst,     make_float4(cc[0], cc[1], cc[2], cc[3]));
        atomicAdd(dst + 1, make_float4(cc[4], cc[5], cc[6], cc[7]));
    }
}

// ---------------------------------------------------------------------------
extern "C" void kernel_launch(void* const* d_in, const int* in_sizes, int n_in,
                              void* d_out, int out_size) {
    const int*   adjacency  = (const int*)  d_in[0];
    const float* features   = (const float*)d_in[1];
    const int*   edge_idxs  = (const int*)  d_in[2];
    const float* edge_feats = (const float*)d_in[3];
    const float* W_dense    = (const float*)d_in[4];
    const float* b_dense    = (const float*)d_in[5];
    const float* W_att      = (const float*)d_in[6];
    const float* b_att      = (const float*)d_in[7];
    float* out = (float*)d_out;

    init_kernel<<<(NV*Uc/4 + 255)/256, 256>>>((float4*)out);
    fdot_kernel<<<(NV*32 + 255)/256, 256>>>(features, W_att, b_att);
    prep_kernel<<<Tc, 128>>>(W_dense, b_dense, W_att);
    logits_kernel<<<(Tc*Ec*32 + 255)/256, 256>>>(edge_feats, edge_idxs);
    vertex_kernel<<<(NV*32 + 255)/256, 256>>>(adjacency);
    dim3 gg((Ec + 127)/128, Tc);
    gemm_scatter_kernel<<<gg, 256>>>(edge_feats, W_dense, b_dense, edge_idxs, out);
}

// round 10
// speedup vs baseline: 1.6503x; 1.6503x over previous
#include <cuda_runtime.h>
#include <cuda_bf16.h>
#include <math.h>
#include <stdint.h>

// Problem constants (fixed by setup_inputs)
#define Bc 2
#define Vc 50000
#define Tc 3
#define Nc 32
#define Fc 128
#define Uc 128
#define Ec 300000
#define NV (Bc*Vc)          // 100000 vertices
#define SLOTS (Tc*Nc)       // 96 slots per vertex
#define NT ((Ec + 127) / 128)   // 2344 tiles per type
#define GRIDX 296

// ---------------------------------------------------------------------------
// Device scratch (no allocation allowed)
// ---------------------------------------------------------------------------
__device__ float    g_logits[Tc*Ec];
__device__ int      g_winner[NV*SLOTS];
__device__ float    g_m[NV];
__device__ float    g_c[NV];
__device__ float    g_fdot[NV];
__device__ float    g_wtilde[Tc*Fc];       // W_t @ W_att[128:]
__device__ float    g_cterm[Tc];           // b_t · W_att[128:]
__device__ uint32_t g_Whi[Tc*128*68];      // W^T hi bf16-pairs, [n][kpair] stride 68
__device__ uint32_t g_Wlo[Tc*128*68];      // W^T lo bf16-pairs

// ---------------------------------------------------------------------------
// Helpers
// ---------------------------------------------------------------------------
__device__ __forceinline__ void split2(float x, float y, uint32_t& hp, uint32_t& lp) {
    __nv_bfloat162 h = __floats2bfloat162_rn(x, y);
    float hx = __bfloat162float(h.x);
    float hy = __bfloat162float(h.y);
    __nv_bfloat162 l = __floats2bfloat162_rn(x - hx, y - hy);
    hp = *reinterpret_cast<uint32_t*>(&h);
    lp = *reinterpret_cast<uint32_t*>(&l);
}

__device__ __forceinline__ void mma16816(float4& d,
        uint32_t a0, uint32_t a1, uint32_t a2, uint32_t a3,
        uint32_t b0, uint32_t b1) {
    asm volatile("mma.sync.aligned.m16n8k16.row.col.f32.bf16.bf16.f32 "
        "{%0,%1,%2,%3}, {%4,%5,%6,%7}, {%8,%9}, {%0,%1,%2,%3};"
        : "+f"(d.x), "+f"(d.y), "+f"(d.z), "+f"(d.w)
        : "r"(a0), "r"(a1), "r"(a2), "r"(a3), "r"(b0), "r"(b1));
}

__device__ __forceinline__ void red2(float* p, float x, float y) {
    asm volatile("red.global.add.v2.f32 [%0], {%1, %2};" :: "l"(p), "f"(x), "f"(y) : "memory");
}

// ---------------------------------------------------------------------------
// K0: init winner grid to -1, out to 0 (vectorized)
// ---------------------------------------------------------------------------
__global__ void init_kernel(float4* __restrict__ out) {
    int i = blockIdx.x * 256 + threadIdx.x;
    if (i < NV*Uc/4)    out[i] = make_float4(0.f, 0.f, 0.f, 0.f);
    if (i < NV*SLOTS/4) ((int4*)g_winner)[i] = make_int4(-1, -1, -1, -1);
}

// ---------------------------------------------------------------------------
// K1: fdot[bv] = features[bv]·W_att[0:128] + b_att
// ---------------------------------------------------------------------------
__global__ void fdot_kernel(const float* __restrict__ feat,
                            const float* __restrict__ Wa,
                            const float* __restrict__ ba) {
    int w = (blockIdx.x * blockDim.x + threadIdx.x) >> 5;
    int lane = threadIdx.x & 31;
    if (w >= NV) return;
    const float4 f = ((const float4*)(feat + (size_t)w * Fc))[lane];
    const float4 a = __ldg(((const float4*)Wa) + lane);
    float s = f.x*a.x + f.y*a.y + f.z*a.z + f.w*a.w;
#pragma unroll
    for (int o = 16; o; o >>= 1) s += __shfl_xor_sync(0xffffffffu, s, o);
    if (lane == 0) g_fdot[w] = s + ba[0];
}

// ---------------------------------------------------------------------------
// K1b: w̃, cterm, and W^T bf16 hi/lo split pair images (stride 68, pad unused)
// ---------------------------------------------------------------------------
__global__ void prep_kernel(const float* __restrict__ Wd,
                            const float* __restrict__ bd,
                            const float* __restrict__ Wa) {
    int t = blockIdx.x;
    int tid = threadIdx.x;   // 256
    if (tid < 128) {
        const float* row = Wd + ((size_t)t * 128 + tid) * 128;
        float s = 0.f;
#pragma unroll 8
        for (int u = 0; u < 128; u++) s += row[u] * __ldg(&Wa[128 + u]);
        g_wtilde[t * 128 + tid] = s;
        if (tid == 0) {
            float cb = 0.f;
            for (int u = 0; u < 128; u++) cb += bd[t * 128 + u] * Wa[128 + u];
            g_cterm[t] = cb;
        }
    }
    for (int i = tid; i < 128 * 64; i += 256) {
        int n  = i >> 6;       // output col (N dim)
        int kp = i & 63;       // k pair
        float w0 = Wd[(size_t)t * 16384 + (size_t)(2*kp)     * 128 + n];
        float w1 = Wd[(size_t)t * 16384 + (size_t)(2*kp + 1) * 128 + n];
        uint32_t hp, lp;
        split2(w0, w1, hp, lp);
        g_Whi[(size_t)t * 8704 + n * 68 + kp] = hp;
        g_Wlo[(size_t)t * 8704 + n * 68 + kp] = lp;
    }
}

// ---------------------------------------------------------------------------
// K2: logits (4 edges/warp, MLP=4): logit = leaky(fdot + ef·w̃ + cterm)
// ---------------------------------------------------------------------------
__global__ void logits_kernel(const float* __restrict__ ef,
                              const int*   __restrict__ eidx) {
    int wg = (blockIdx.x * 256 + threadIdx.x) >> 5;
    int lane = threadIdx.x & 31;
    if (wg >= Tc * (Ec/4)) return;
    int t = wg / (Ec/4);
    int e0 = (wg - t * (Ec/4)) * 4;
    const float4* base = (const float4*)(ef + ((size_t)t * Ec + e0) * 128);
    float4 a0 = base[lane];
    float4 a1 = base[32 + lane];
    float4 a2 = base[64 + lane];
    float4 a3 = base[96 + lane];
    const float4 w = __ldg(((const float4*)(g_wtilde + t * 128)) + lane);
    float s0 = a0.x*w.x + a0.y*w.y + a0.z*w.z + a0.w*w.w;
    float s1 = a1.x*w.x + a1.y*w.y + a1.z*w.z + a1.w*w.w;
    float s2 = a2.x*w.x + a2.y*w.y + a2.z*w.z + a2.w*w.w;
    float s3 = a3.x*w.x + a3.y*w.y + a3.z*w.z + a3.w*w.w;
#pragma unroll
    for (int o = 16; o; o >>= 1) {
        s0 += __shfl_xor_sync(0xffffffffu, s0, o);
        s1 += __shfl_xor_sync(0xffffffffu, s1, o);
        s2 += __shfl_xor_sync(0xffffffffu, s2, o);
        s3 += __shfl_xor_sync(0xffffffffu, s3, o);
    }
    if (lane < 4) {
        float sv = (lane == 0) ? s0 : (lane == 1) ? s1 : (lane == 2) ? s2 : s3;
        int e = e0 + lane;
        const int* ei = eidx + ((size_t)t * Ec + e) * 3;
        int b = ei[0], v = ei[1], sl = ei[2];
        int bv = b * Vc + v;
        float x = g_fdot[bv] + sv + g_cterm[t];
        float logit = (x > 0.0f) ? x : 0.3f * x;
        g_logits[t * Ec + e] = logit;
        atomicMax(&g_winner[bv * SLOTS + t * Nc + sl], e);
    }
}

// ---------------------------------------------------------------------------
// K3: per-vertex softmax stats
// ---------------------------------------------------------------------------
__global__ void vertex_kernel(const int* __restrict__ adj) {
    int vert = (blockIdx.x * blockDim.x + threadIdx.x) >> 5;
    int lane = threadIdx.x & 31;
    if (vert >= NV) return;
    const int base = vert * SLOTS;
    float l[3];
    int deg = 0;
#pragma unroll
    for (int i = 0; i < 3; i++) {
        int slot = i * 32 + lane;
        int w = g_winner[base + slot];
        deg += (adj[base + slot] >= 0) ? 1 : 0;
        l[i] = (w >= 0) ? g_logits[i * Ec + w] : -200.0f;
    }
    float m = fmaxf(fmaxf(l[0], l[1]), l[2]);
#pragma unroll
    for (int o = 16; o; o >>= 1) m = fmaxf(m, __shfl_xor_sync(0xffffffffu, m, o));
    float den = expf(l[0] - m) + expf(l[1] - m) + expf(l[2] - m);
#pragma unroll
    for (int o = 16; o; o >>= 1) {
        den += __shfl_xor_sync(0xffffffffu, den, o);
        deg += __shfl_xor_sync(0xffffffffu, deg, o);
    }
    if (lane == 0) { g_m[vert] = m; g_c[vert] = (float)deg / den; }
}

// ---------------------------------------------------------------------------
// K4: bf16x3 split HMMA GEMM + fused weighted scatter. Persistent.
// SMEM word layout (uint32 words), total 28032 words = 112128 B:
//   [0      .. 8704)   W_hi [n][kpair], stride 68 (bank-conflict-free)
//   [8704   .. 17408)  W_lo
//   [17408  .. 27648)  A chunks: 2 bufs × {hi 2560, lo 2560}, [row][kpair] stride 20
//   [27648  .. 27776)  satt
//   [27776  .. 27904)  sbv
//   [27904  .. 28032)  sbias
// ---------------------------------------------------------------------------
#define W_HI_OFF 0
#define W_LO_OFF 8704
#define A_OFF    17408
#define SATT_OFF 27648
#define SBV_OFF  27776
#define SBIAS_OFF 27904
#define SMEM_WORDS 28032
#define SMEM_BYTES (SMEM_WORDS*4)

__global__ __launch_bounds__(256, 2)
void gemm_hmma(const float* __restrict__ ef,    // [T,E,128]
               const float* __restrict__ bd,    // [T,128]
               const int*   __restrict__ eidx,  // [T,E,3]
               float* __restrict__ out)
{
    extern __shared__ uint32_t sm[];
    const int tid  = threadIdx.x;
    const int lane = tid & 31;
    const int wid  = tid >> 5;
    const int wm   = wid >> 2;          // 0..1 : row-block of 64
    const int wn   = wid & 3;           // 0..3 : col-block of 32
    const int gi   = lane >> 2;         // 0..7
    const int cl   = lane & 3;          // 0..3
    const int t    = blockIdx.y;

    // --- CTA prologue: W hi/lo + bias into smem
    {
        const uint4* srch = (const uint4*)(g_Whi + (size_t)t * 8704);
        const uint4* srcl = (const uint4*)(g_Wlo + (size_t)t * 8704);
        uint4* dsth = (uint4*)(sm + W_HI_OFF);
        uint4* dstl = (uint4*)(sm + W_LO_OFF);
        for (int i = tid; i < 2176; i += 256) { dsth[i] = srch[i]; dstl[i] = srcl[i]; }
        if (tid < 128) ((float*)(sm + SBIAS_OFF))[tid] = bd[t * 128 + tid];
    }
    __syncthreads();

    const uint32_t* sWhi = sm + W_HI_OFF;
    const uint32_t* sWlo = sm + W_LO_OFF;
    float* satt = (float*)(sm + SATT_OFF);
    int*   sbv  = (int*)(sm + SBV_OFF);
    const float* sbias = (const float*)(sm + SBIAS_OFF);

    const int srow = tid >> 1;          // staging row 0..127
    const int skh  = tid & 1;           // staging k-half

    for (int tile = blockIdx.x; tile < NT; tile += GRIDX) {
        const int e0 = tile * 128;
        const int rowsv = min(128, Ec - e0);
        const float* A = ef + ((size_t)t * Ec + e0) * 128;

        // --- att prefetch (long-latency chain overlapped with whole tile)
        float attR = 0.f; int bvR = 0;
        if (tid < 128 && tid < rowsv) {
            int e = e0 + tid;
            const int* ei = eidx + ((size_t)t * Ec + e) * 3;
            int b = ei[0], v = ei[1], sl = ei[2];
            int bv = b * Vc + v;
            int w = g_winner[bv * SLOTS + t * Nc + sl];
            attR = expf(g_logits[t * Ec + w] - g_m[bv]) * g_c[bv];
            bvR = bv;
        }

        float4 acc[4][4];
#pragma unroll
        for (int i = 0; i < 4; i++)
#pragma unroll
            for (int j = 0; j < 4; j++) acc[i][j] = make_float4(0.f,0.f,0.f,0.f);

        // --- stage chunk 0
        float4 rg[4];
        {
            const float4* src = (const float4*)(A + (size_t)srow * 128 + skh * 16);
#pragma unroll
            for (int j = 0; j < 4; j++)
                rg[j] = (srow < rowsv) ? src[j] : make_float4(0.f,0.f,0.f,0.f);
            uint32_t* dh = sm + A_OFF + srow * 20 + skh * 8;
            uint32_t* dl = dh + 2560;
            uint32_t hv[8], lv[8];
#pragma unroll
            for (int j = 0; j < 4; j++) {
                split2(rg[j].x, rg[j].y, hv[2*j],   lv[2*j]);
                split2(rg[j].z, rg[j].w, hv[2*j+1], lv[2*j+1]);
            }
            *(uint4*)&dh[0] = *(uint4*)&hv[0]; *(uint4*)&dh[4] = *(uint4*)&hv[4];
            *(uint4*)&dl[0] = *(uint4*)&lv[0]; *(uint4*)&dl[4] = *(uint4*)&lv[4];
        }
        __syncthreads();

        // --- chunk pipeline: LDG c+1 -> HMMA c -> STS c+1 -> sync
#pragma unroll
        for (int c = 0; c < 4; c++) {
            if (c < 3) {
                const float4* src = (const float4*)(A + (size_t)srow * 128 + (c+1) * 32 + skh * 16);
#pragma unroll
                for (int j = 0; j < 4; j++)
                    rg[j] = (srow < rowsv) ? src[j] : make_float4(0.f,0.f,0.f,0.f);
            }

            const uint32_t* sAh = sm + A_OFF + (c & 1) * 5120;
            const uint32_t* sAl = sAh + 2560;
#pragma unroll
            for (int kk = 0; kk < 2; kk++) {
                const int pb = kk * 8 + cl;
                uint32_t bh[4][2], bl[4][2];
#pragma unroll
                for (int nf = 0; nf < 4; nf++) {
                    int w0 = (wn*32 + nf*8 + gi) * 68 + c * 16 + pb;
                    bh[nf][0] = sWhi[w0]; bh[nf][1] = sWhi[w0 + 4];
                    bl[nf][0] = sWlo[w0]; bl[nf][1] = sWlo[w0 + 4];
                }
#pragma unroll
                for (int mf = 0; mf < 4; mf++) {
                    int a0i = (wm*64 + mf*16 + gi) * 20 + pb;
                    uint32_t ah0 = sAh[a0i],        ah1 = sAh[a0i + 160];
                    uint32_t ah2 = sAh[a0i + 4],    ah3 = sAh[a0i + 164];
                    uint32_t al0 = sAl[a0i],        al1 = sAl[a0i + 160];
                    uint32_t al2 = sAl[a0i + 4],    al3 = sAl[a0i + 164];
#pragma unroll
                    for (int nf = 0; nf < 4; nf++)
                        mma16816(acc[mf][nf], ah0, ah1, ah2, ah3, bh[nf][0], bh[nf][1]);
#pragma unroll
                    for (int nf = 0; nf < 4; nf++)
                        mma16816(acc[mf][nf], ah0, ah1, ah2, ah3, bl[nf][0], bl[nf][1]);
#pragma unroll
                    for (int nf = 0; nf < 4; nf++)
                        mma16816(acc[mf][nf], al0, al1, al2, al3, bh[nf][0], bh[nf][1]);
                }
            }

            if (c < 3) {
                uint32_t* dh = sm + A_OFF + ((c+1) & 1) * 5120 + srow * 20 + skh * 8;
                uint32_t* dl = dh + 2560;
                uint32_t hv[8], lv[8];
#pragma unroll
                for (int j = 0; j < 4; j++) {
                    split2(rg[j].x, rg[j].y, hv[2*j],   lv[2*j]);
                    split2(rg[j].z, rg[j].w, hv[2*j+1], lv[2*j+1]);
                }
                *(uint4*)&dh[0] = *(uint4*)&hv[0]; *(uint4*)&dh[4] = *(uint4*)&hv[4];
                *(uint4*)&dl[0] = *(uint4*)&lv[0]; *(uint4*)&dl[4] = *(uint4*)&lv[4];
            }
            __syncthreads();
        }

        // --- publish att/bv, then epilogue
        if (tid < 128) { satt[tid] = attR; sbv[tid] = bvR; }
        __syncthreads();

#pragma unroll
        for (int mf = 0; mf < 4; mf++) {
            int r0 = wm*64 + mf*16 + gi;
            int r1 = r0 + 8;
            float a0 = satt[r0], a1 = satt[r1];
            size_t o0 = (size_t)sbv[r0] * 128, o1 = (size_t)sbv[r1] * 128;
#pragma unroll
            for (int nf = 0; nf < 4; nf++) {
                int col = wn*32 + nf*8 + cl*2;
                float bx = sbias[col], by = sbias[col+1];
                float4 ac = acc[mf][nf];
                red2(out + o0 + col, (ac.x + bx) * a0, (ac.y + by) * a0);
                red2(out + o1 + col, (ac.z + bx) * a1, (ac.w + by) * a1);
            }
        }
        __syncthreads();
    }
}

// ---------------------------------------------------------------------------
extern "C" void kernel_launch(void* const* d_in, const int* in_sizes, int n_in,
                              void* d_out, int out_size) {
    const int*   adjacency  = (const int*)  d_in[0];
    const float* features   = (const float*)d_in[1];
    const int*   edge_idxs  = (const int*)  d_in[2];
    const float* edge_feats = (const float*)d_in[3];
    const float* W_dense    = (const float*)d_in[4];
    const float* b_dense    = (const float*)d_in[5];
    const float* W_att      = (const float*)d_in[6];
    const float* b_att      = (const float*)d_in[7];
    float* out = (float*)d_out;

    cudaFuncSetAttribute(gemm_hmma,
                         cudaFuncAttributeMaxDynamicSharedMemorySize, SMEM_BYTES);

    init_kernel<<<(NV*Uc/4 + 255)/256, 256>>>((float4*)out);
    fdot_kernel<<<(NV*32 + 255)/256, 256>>>(features, W_att, b_att);
    prep_kernel<<<Tc, 256>>>(W_dense, b_dense, W_att);
    logits_kernel<<<(Tc*(Ec/4)*32 + 255)/256, 256>>>(edge_feats, edge_idxs);
    vertex_kernel<<<(NV*32 + 255)/256, 256>>>(adjacency);
    dim3 gg(GRIDX, 3);
    gemm_hmma<<<gg, 256, SMEM_BYTES>>>(edge_feats, b_dense, edge_idxs, out);
}

// round 12
// speedup vs baseline: 1.6695x; 1.0116x over previous
#include <cuda_runtime.h>
#include <cuda_bf16.h>
#include <math.h>
#include <stdint.h>

// Problem constants (fixed by setup_inputs)
#define Bc 2
#define Vc 50000
#define Tc 3
#define Nc 32
#define Fc 128
#define Uc 128
#define Ec 300000
#define NV (Bc*Vc)          // 100000 vertices
#define SLOTS (Tc*Nc)       // 96 slots per vertex
#define NT ((Ec + 127) / 128)   // 2344 tiles per type
#define GRIDX 296

// ---------------------------------------------------------------------------
// Device scratch (no allocation allowed)
// ---------------------------------------------------------------------------
__device__ float    g_logits[Tc*Ec];
__device__ int      g_winner[NV*SLOTS];
__device__ float    g_m[NV];
__device__ float    g_c[NV];
__device__ float    g_fdot[NV];
__device__ float    g_wtilde[Tc*Fc];       // W_t @ W_att[128:]
__device__ float    g_cterm[Tc];           // b_t · W_att[128:]
__device__ uint32_t g_Whi[Tc*128*68];      // W^T hi bf16-pairs, [n][kpair] stride 68
__device__ uint32_t g_Wlo[Tc*128*68];      // W^T lo bf16-pairs

// ---------------------------------------------------------------------------
// Helpers
// ---------------------------------------------------------------------------
__device__ __forceinline__ void split2(float x, float y, uint32_t& hp, uint32_t& lp) {
    __nv_bfloat162 h = __floats2bfloat162_rn(x, y);
    float hx = __bfloat162float(h.x);
    float hy = __bfloat162float(h.y);
    __nv_bfloat162 l = __floats2bfloat162_rn(x - hx, y - hy);
    hp = *reinterpret_cast<uint32_t*>(&h);
    lp = *reinterpret_cast<uint32_t*>(&l);
}

__device__ __forceinline__ void mma16816(float4& d,
        uint32_t a0, uint32_t a1, uint32_t a2, uint32_t a3,
        uint32_t b0, uint32_t b1) {
    asm volatile("mma.sync.aligned.m16n8k16.row.col.f32.bf16.bf16.f32 "
        "{%0,%1,%2,%3}, {%4,%5,%6,%7}, {%8,%9}, {%0,%1,%2,%3};"
        : "+f"(d.x), "+f"(d.y), "+f"(d.z), "+f"(d.w)
        : "r"(a0), "r"(a1), "r"(a2), "r"(a3), "r"(b0), "r"(b1));
}

__device__ __forceinline__ void ldsm4(uint32_t& r0, uint32_t& r1,
                                      uint32_t& r2, uint32_t& r3, uint32_t addr) {
    asm volatile("ldmatrix.sync.aligned.m8n8.x4.shared.b16 {%0,%1,%2,%3}, [%4];"
        : "=r"(r0), "=r"(r1), "=r"(r2), "=r"(r3) : "r"(addr));
}

__device__ __forceinline__ void red2(float* p, float x, float y) {
    asm volatile("red.global.add.v2.f32 [%0], {%1, %2};" :: "l"(p), "f"(x), "f"(y) : "memory");
}

__device__ __forceinline__ uint32_t smem_u32(const void* p) {
    uint32_t a;
    asm("{ .reg .u64 t; cvta.to.shared.u64 t, %1; cvt.u32.u64 %0, t; }" : "=r"(a) : "l"(p));
    return a;
}

// ---------------------------------------------------------------------------
// K0: init winner grid to -1, out to 0 (vectorized)
// ---------------------------------------------------------------------------
__global__ void init_kernel(float4* __restrict__ out) {
    int i = blockIdx.x * 256 + threadIdx.x;
    if (i < NV*Uc/4)    out[i] = make_float4(0.f, 0.f, 0.f, 0.f);
    if (i < NV*SLOTS/4) ((int4*)g_winner)[i] = make_int4(-1, -1, -1, -1);
}

// ---------------------------------------------------------------------------
// K1: fdot[bv] = features[bv]·W_att[0:128] + b_att
// ---------------------------------------------------------------------------
__global__ void fdot_kernel(const float* __restrict__ feat,
                            const float* __restrict__ Wa,
                            const float* __restrict__ ba) {
    int w = (blockIdx.x * blockDim.x + threadIdx.x) >> 5;
    int lane = threadIdx.x & 31;
    if (w >= NV) return;
    const float4 f = ((const float4*)(feat + (size_t)w * Fc))[lane];
    const float4 a = __ldg(((const float4*)Wa) + lane);
    float s = f.x*a.x + f.y*a.y + f.z*a.z + f.w*a.w;
#pragma unroll
    for (int o = 16; o; o >>= 1) s += __shfl_xor_sync(0xffffffffu, s, o);
    if (lane == 0) g_fdot[w] = s + ba[0];
}

// ---------------------------------------------------------------------------
// K1b: w̃, cterm, and W^T bf16 hi/lo split pair images (stride 68)
// ---------------------------------------------------------------------------
__global__ void prep_kernel(const float* __restrict__ Wd,
                            const float* __restrict__ bd,
                            const float* __restrict__ Wa) {
    int t = blockIdx.x;
    int tid = threadIdx.x;   // 256
    if (tid < 128) {
        const float* row = Wd + ((size_t)t * 128 + tid) * 128;
        float s = 0.f;
#pragma unroll 8
        for (int u = 0; u < 128; u++) s += row[u] * __ldg(&Wa[128 + u]);
        g_wtilde[t * 128 + tid] = s;
        if (tid == 0) {
            float cb = 0.f;
            for (int u = 0; u < 128; u++) cb += bd[t * 128 + u] * Wa[128 + u];
            g_cterm[t] = cb;
        }
    }
    for (int i = tid; i < 128 * 64; i += 256) {
        int n  = i >> 6;       // output col (N dim)
        int kp = i & 63;       // k pair
        float w0 = Wd[(size_t)t * 16384 + (size_t)(2*kp)     * 128 + n];
        float w1 = Wd[(size_t)t * 16384 + (size_t)(2*kp + 1) * 128 + n];
        uint32_t hp, lp;
        split2(w0, w1, hp, lp);
        g_Whi[(size_t)t * 8704 + n * 68 + kp] = hp;
        g_Wlo[(size_t)t * 8704 + n * 68 + kp] = lp;
    }
}

// ---------------------------------------------------------------------------
// K2: logits (4 edges/warp, MLP=4): logit = leaky(fdot + ef·w̃ + cterm)
// ---------------------------------------------------------------------------
__global__ void logits_kernel(const float* __restrict__ ef,
                              const int*   __restrict__ eidx) {
    int wg = (blockIdx.x * 256 + threadIdx.x) >> 5;
    int lane = threadIdx.x & 31;
    if (wg >= Tc * (Ec/4)) return;
    int t = wg / (Ec/4);
    int e0 = (wg - t * (Ec/4)) * 4;
    const float4* base = (const float4*)(ef + ((size_t)t * Ec + e0) * 128);
    float4 a0 = base[lane];
    float4 a1 = base[32 + lane];
    float4 a2 = base[64 + lane];
    float4 a3 = base[96 + lane];
    const float4 w = __ldg(((const float4*)(g_wtilde + t * 128)) + lane);
    float s0 = a0.x*w.x + a0.y*w.y + a0.z*w.z + a0.w*w.w;
    float s1 = a1.x*w.x + a1.y*w.y + a1.z*w.z + a1.w*w.w;
    float s2 = a2.x*w.x + a2.y*w.y + a2.z*w.z + a2.w*w.w;
    float s3 = a3.x*w.x + a3.y*w.y + a3.z*w.z + a3.w*w.w;
#pragma unroll
    for (int o = 16; o; o >>= 1) {
        s0 += __shfl_xor_sync(0xffffffffu, s0, o);
        s1 += __shfl_xor_sync(0xffffffffu, s1, o);
        s2 += __shfl_xor_sync(0xffffffffu, s2, o);
        s3 += __shfl_xor_sync(0xffffffffu, s3, o);
    }
    if (lane < 4) {
        float sv = (lane == 0) ? s0 : (lane == 1) ? s1 : (lane == 2) ? s2 : s3;
        int e = e0 + lane;
        const int* ei = eidx + ((size_t)t * Ec + e) * 3;
        int b = ei[0], v = ei[1], sl = ei[2];
        int bv = b * Vc + v;
        float x = g_fdot[bv] + sv + g_cterm[t];
        float logit = (x > 0.0f) ? x : 0.3f * x;
        g_logits[t * Ec + e] = logit;
        atomicMax(&g_winner[bv * SLOTS + t * Nc + sl], e);
    }
}

// ---------------------------------------------------------------------------
// K3: per-vertex softmax stats
// ---------------------------------------------------------------------------
__global__ void vertex_kernel(const int* __restrict__ adj) {
    int vert = (blockIdx.x * blockDim.x + threadIdx.x) >> 5;
    int lane = threadIdx.x & 31;
    if (vert >= NV) return;
    const int base = vert * SLOTS;
    float l[3];
    int deg = 0;
#pragma unroll
    for (int i = 0; i < 3; i++) {
        int slot = i * 32 + lane;
        int w = g_winner[base + slot];
        deg += (adj[base + slot] >= 0) ? 1 : 0;
        l[i] = (w >= 0) ? g_logits[i * Ec + w] : -200.0f;
    }
    float m = fmaxf(fmaxf(l[0], l[1]), l[2]);
#pragma unroll
    for (int o = 16; o; o >>= 1) m = fmaxf(m, __shfl_xor_sync(0xffffffffu, m, o));
    float den = expf(l[0] - m) + expf(l[1] - m) + expf(l[2] - m);
#pragma unroll
    for (int o = 16; o; o >>= 1) {
        den += __shfl_xor_sync(0xffffffffu, den, o);
        deg += __shfl_xor_sync(0xffffffffu, deg, o);
    }
    if (lane == 0) { g_m[vert] = m; g_c[vert] = (float)deg / den; }
}

// ---------------------------------------------------------------------------
// K4: bf16x3 split HMMA GEMM + fused weighted scatter. Persistent.
// Fragment loads via ldmatrix.m8n8.x4 (24 LDSM vs 96 scalar LDS per warp-chunk).
// NOTE: B smem holds FULL K (64 kpairs) -> chunk offset c*16 kpairs = c*64 bytes
// must be added to B fragment addresses (this was the R11 bug).
// SMEM word layout (uint32 words), total 28032 words = 112128 B:
//   [0      .. 8704)   W_hi [n][kpair], stride 68 (bank-conflict-free)
//   [8704   .. 17408)  W_lo
//   [17408  .. 27648)  A chunks: 2 bufs × {hi 2560, lo 2560}, [row][kpair] stride 20
//   [27648  .. 27776)  satt
//   [27776  .. 27904)  sbv
//   [27904  .. 28032)  sbias
// ---------------------------------------------------------------------------
#define W_HI_OFF 0
#define W_LO_OFF 8704
#define A_OFF    17408
#define SATT_OFF 27648
#define SBV_OFF  27776
#define SBIAS_OFF 27904
#define SMEM_WORDS 28032
#define SMEM_BYTES (SMEM_WORDS*4)

__global__ __launch_bounds__(256, 2)
void gemm_hmma(const float* __restrict__ ef,    // [T,E,128]
               const float* __restrict__ bd,    // [T,128]
               const int*   __restrict__ eidx,  // [T,E,3]
               float* __restrict__ out)
{
    extern __shared__ uint32_t sm[];
    const int tid  = threadIdx.x;
    const int lane = tid & 31;
    const int wid  = tid >> 5;
    const int wm   = wid >> 2;          // 0..1 : row-block of 64
    const int wn   = wid & 3;           // 0..3 : col-block of 32
    const int gi   = lane >> 2;         // 0..7
    const int t    = blockIdx.y;

    // --- CTA prologue: W hi/lo + bias into smem
    {
        const uint4* srch = (const uint4*)(g_Whi + (size_t)t * 8704);
        const uint4* srcl = (const uint4*)(g_Wlo + (size_t)t * 8704);
        uint4* dsth = (uint4*)(sm + W_HI_OFF);
        uint4* dstl = (uint4*)(sm + W_LO_OFF);
        for (int i = tid; i < 2176; i += 256) { dsth[i] = srch[i]; dstl[i] = srcl[i]; }
        if (tid < 128) ((float*)(sm + SBIAS_OFF))[tid] = bd[t * 128 + tid];
    }
    __syncthreads();

    float* satt = (float*)(sm + SATT_OFF);
    int*   sbv  = (int*)(sm + SBV_OFF);
    const float* sbias = (const float*)(sm + SBIAS_OFF);

    // --- per-lane ldmatrix base addresses (byte, shared space)
    const uint32_t smb = smem_u32(sm);
    const int m4 = lane >> 3;           // matrix index 0..3
    const int lr = lane & 7;            // row within matrix
    // A: M0 rows+0 kp+0 | M1 rows+8 kp+0 | M2 rows+0 kp+4 | M3 rows+8 kp+4
    const uint32_t a_base = smb + A_OFF*4 +
        (((wm*64 + (m4 & 1)*8 + lr) * 20) + (m4 >> 1)*4) * 4;
    // B: M0 n+0 kp+0 | M1 n+0 kp+4 | M2 n+8 kp+0 | M3 n+8 kp+4
    const uint32_t b_base_hi = smb + W_HI_OFF*4 +
        (((wn*32 + (m4 >> 1)*8 + lr) * 68) + (m4 & 1)*4) * 4;
    const uint32_t b_base_lo = b_base_hi + 8704*4;

    const int srow = tid >> 1;          // staging row 0..127
    const int skh  = tid & 1;           // staging k-half

    for (int tile = blockIdx.x; tile < NT; tile += GRIDX) {
        const int e0 = tile * 128;
        const int rowsv = min(128, Ec - e0);
        const float* A = ef + ((size_t)t * Ec + e0) * 128;

        // --- att prefetch (long-latency chain overlapped with whole tile)
        float attR = 0.f; int bvR = 0;
        if (tid < 128 && tid < rowsv) {
            int e = e0 + tid;
            const int* ei = eidx + ((size_t)t * Ec + e) * 3;
            int b = ei[0], v = ei[1], sl = ei[2];
            int bv = b * Vc + v;
            int w = g_winner[bv * SLOTS + t * Nc + sl];
            attR = expf(g_logits[t * Ec + w] - g_m[bv]) * g_c[bv];
            bvR = bv;
        }

        float4 acc[4][4];
#pragma unroll
        for (int i = 0; i < 4; i++)
#pragma unroll
            for (int j = 0; j < 4; j++) acc[i][j] = make_float4(0.f,0.f,0.f,0.f);

        // --- stage chunk 0
        float4 rg[4];
        {
            const float4* src = (const float4*)(A + (size_t)srow * 128 + skh * 16);
#pragma unroll
            for (int j = 0; j < 4; j++)
                rg[j] = (srow < rowsv) ? src[j] : make_float4(0.f,0.f,0.f,0.f);
            uint32_t* dh = sm + A_OFF + srow * 20 + skh * 8;
            uint32_t* dl = dh + 2560;
            uint32_t hv[8], lv[8];
#pragma unroll
            for (int j = 0; j < 4; j++) {
                split2(rg[j].x, rg[j].y, hv[2*j],   lv[2*j]);
                split2(rg[j].z, rg[j].w, hv[2*j+1], lv[2*j+1]);
            }
            *(uint4*)&dh[0] = *(uint4*)&hv[0]; *(uint4*)&dh[4] = *(uint4*)&hv[4];
            *(uint4*)&dl[0] = *(uint4*)&lv[0]; *(uint4*)&dl[4] = *(uint4*)&lv[4];
        }
        __syncthreads();

        // --- chunk pipeline: LDG c+1 -> HMMA c -> STS c+1 -> sync
#pragma unroll
        for (int c = 0; c < 4; c++) {
            if (c < 3) {
                const float4* src = (const float4*)(A + (size_t)srow * 128 + (c+1) * 32 + skh * 16);
#pragma unroll
                for (int j = 0; j < 4; j++)
                    rg[j] = (srow < rowsv) ? src[j] : make_float4(0.f,0.f,0.f,0.f);
            }

            const uint32_t abase = a_base + (c & 1) * 20480;
            const uint32_t bchunk = (uint32_t)(c * 64);   // c*16 kpairs = c*64 bytes
#pragma unroll
            for (int kk = 0; kk < 2; kk++) {
                const uint32_t kkb = kk * 32;
                uint32_t bh[8], bl[8];
                ldsm4(bh[0], bh[1], bh[2], bh[3], b_base_hi + bchunk + kkb);          // nf0, nf1
                ldsm4(bh[4], bh[5], bh[6], bh[7], b_base_hi + bchunk + 4352 + kkb);   // nf2, nf3
                ldsm4(bl[0], bl[1], bl[2], bl[3], b_base_lo + bchunk + kkb);
                ldsm4(bl[4], bl[5], bl[6], bl[7], b_base_lo + bchunk + 4352 + kkb);
#pragma unroll
                for (int mf = 0; mf < 4; mf++) {
                    uint32_t ah[4], al[4];
                    ldsm4(ah[0], ah[1], ah[2], ah[3], abase + mf*1280 + kkb);
                    ldsm4(al[0], al[1], al[2], al[3], abase + mf*1280 + kkb + 10240);
#pragma unroll
                    for (int nf = 0; nf < 4; nf++)
                        mma16816(acc[mf][nf], ah[0], ah[1], ah[2], ah[3], bh[2*nf], bh[2*nf+1]);
#pragma unroll
                    for (int nf = 0; nf < 4; nf++)
                        mma16816(acc[mf][nf], ah[0], ah[1], ah[2], ah[3], bl[2*nf], bl[2*nf+1]);
#pragma unroll
                    for (int nf = 0; nf < 4; nf++)
                        mma16816(acc[mf][nf], al[0], al[1], al[2], al[3], bh[2*nf], bh[2*nf+1]);
                }
            }

            if (c < 3) {
                uint32_t* dh = sm + A_OFF + ((c+1) & 1) * 5120 + srow * 20 + skh * 8;
                uint32_t* dl = dh + 2560;
                uint32_t hv[8], lv[8];
#pragma unroll
                for (int j = 0; j < 4; j++) {
                    split2(rg[j].x, rg[j].y, hv[2*j],   lv[2*j]);
                    split2(rg[j].z, rg[j].w, hv[2*j+1], lv[2*j+1]);
                }
                *(uint4*)&dh[0] = *(uint4*)&hv[0]; *(uint4*)&dh[4] = *(uint4*)&hv[4];
                *(uint4*)&dl[0] = *(uint4*)&lv[0]; *(uint4*)&dl[4] = *(uint4*)&lv[4];
            }
            __syncthreads();
        }

        // --- publish att/bv, then epilogue
        if (tid < 128) { satt[tid] = attR; sbv[tid] = bvR; }
        __syncthreads();

#pragma unroll
        for (int mf = 0; mf < 4; mf++) {
            int r0 = wm*64 + mf*16 + gi;
            int r1 = r0 + 8;
            float a0 = satt[r0], a1 = satt[r1];
            size_t o0 = (size_t)sbv[r0] * 128, o1 = (size_t)sbv[r1] * 128;
#pragma unroll
            for (int nf = 0; nf < 4; nf++) {
                int col = wn*32 + nf*8 + (lane & 3)*2;
                float bx = sbias[col], by = sbias[col+1];
                float4 ac = acc[mf][nf];
                red2(out + o0 + col, (ac.x + bx) * a0, (ac.y + by) * a0);
                red2(out + o1 + col, (ac.z + bx) * a1, (ac.w + by) * a1);
            }
        }
        __syncthreads();
    }
}

// ---------------------------------------------------------------------------
extern "C" void kernel_launch(void* const* d_in, const int* in_sizes, int n_in,
                              void* d_out, int out_size) {
    const int*   adjacency  = (const int*)  d_in[0];
    const float* features   = (const float*)d_in[1];
    const int*   edge_idxs  = (const int*)  d_in[2];
    const float* edge_feats = (const float*)d_in[3];
    const float* W_dense    = (const float*)d_in[4];
    const float* b_dense    = (const float*)d_in[5];
    const float* W_att      = (const float*)d_in[6];
    const float* b_att      = (const float*)d_in[7];
    float* out = (float*)d_out;

    cudaFuncSetAttribute(gemm_hmma,
                         cudaFuncAttributeMaxDynamicSharedMemorySize, SMEM_BYTES);

    init_kernel<<<(NV*Uc/4 + 255)/256, 256>>>((float4*)out);
    fdot_kernel<<<(NV*32 + 255)/256, 256>>>(features, W_att, b_att);
    prep_kernel<<<Tc, 256>>>(W_dense, b_dense, W_att);
    logits_kernel<<<(Tc*(Ec/4)*32 + 255)/256, 256>>>(edge_feats, edge_idxs);
    vertex_kernel<<<(NV*32 + 255)/256, 256>>>(adjacency);
    dim3 gg(GRIDX, 3);
    gemm_hmma<<<gg, 256, SMEM_BYTES>>>(edge_feats, b_dense, edge_idxs, out);
}

// round 14
// speedup vs baseline: 1.6990x; 1.0177x over previous
#include <cuda_runtime.h>
#include <cuda_bf16.h>
#include <math.h>
#include <stdint.h>

// Problem constants (fixed by setup_inputs)
#define Bc 2
#define Vc 50000
#define Tc 3
#define Nc 32
#define Fc 128
#define Uc 128
#define Ec 300000
#define NV (Bc*Vc)          // 100000 vertices
#define SLOTS (Tc*Nc)       // 96 slots per vertex
#define NT ((Ec + 127) / 128)   // 2344 tiles per type
#define EP (NT*128)             // 300032 padded edge stride
#define GRIDX 296

// ---------------------------------------------------------------------------
// Device scratch (no allocation allowed)
// ---------------------------------------------------------------------------
__device__ float    g_logits[Tc*Ec];
__device__ int      g_winner[NV*SLOTS];
__device__ float    g_m[NV];
__device__ float    g_c[NV];
__device__ float    g_fdot[NV];
__device__ float    g_wtilde[Tc*Fc];       // W_t @ W_att[128:]
__device__ float    g_cterm[Tc];           // b_t · W_att[128:]
__device__ uint32_t g_Whi[Tc*128*64];      // W^T hi bf16-pairs, [n][kpair] unpadded
__device__ uint32_t g_Wlo[Tc*128*64];      // W^T lo
__device__ uint32_t g_Ahi[(size_t)Tc*EP*64];  // ef hi bf16-pairs, row-major
__device__ uint32_t g_Alo[(size_t)Tc*EP*64];  // ef lo

// ---------------------------------------------------------------------------
// Helpers
// ---------------------------------------------------------------------------
__device__ __forceinline__ void split2(float x, float y, uint32_t& hp, uint32_t& lp) {
    __nv_bfloat162 h = __floats2bfloat162_rn(x, y);
    float hx = __bfloat162float(h.x);
    float hy = __bfloat162float(h.y);
    __nv_bfloat162 l = __floats2bfloat162_rn(x - hx, y - hy);
    hp = *reinterpret_cast<uint32_t*>(&h);
    lp = *reinterpret_cast<uint32_t*>(&l);
}

__device__ __forceinline__ void mma16816(float4& d,
        uint32_t a0, uint32_t a1, uint32_t a2, uint32_t a3,
        uint32_t b0, uint32_t b1) {
    asm volatile("mma.sync.aligned.m16n8k16.row.col.f32.bf16.bf16.f32 "
        "{%0,%1,%2,%3}, {%4,%5,%6,%7}, {%8,%9}, {%0,%1,%2,%3};"
        : "+f"(d.x), "+f"(d.y), "+f"(d.z), "+f"(d.w)
        : "r"(a0), "r"(a1), "r"(a2), "r"(a3), "r"(b0), "r"(b1));
}

__device__ __forceinline__ void ldsm4(uint32_t& r0, uint32_t& r1,
                                      uint32_t& r2, uint32_t& r3, uint32_t addr) {
    asm volatile("ldmatrix.sync.aligned.m8n8.x4.shared.b16 {%0,%1,%2,%3}, [%4];"
        : "=r"(r0), "=r"(r1), "=r"(r2), "=r"(r3) : "r"(addr));
}

__device__ __forceinline__ void red2(float* p, float x, float y) {
    asm volatile("red.global.add.v2.f32 [%0], {%1, %2};" :: "l"(p), "f"(x), "f"(y) : "memory");
}

__device__ __forceinline__ uint32_t smem_u32(const void* p) {
    uint32_t a;
    asm("{ .reg .u64 t; cvta.to.shared.u64 t, %1; cvt.u32.u64 %0, t; }" : "=r"(a) : "l"(p));
    return a;
}

__device__ __forceinline__ void cpa16(uint32_t dst, const void* src) {
    asm volatile("cp.async.cg.shared.global [%0], [%1], 16;" :: "r"(dst), "l"(src) : "memory");
}
#define CP_COMMIT() asm volatile("cp.async.commit_group;" ::: "memory")

// ---------------------------------------------------------------------------
// K0: init winner grid to -1, out to 0, zero A pad rows
// ---------------------------------------------------------------------------
__global__ void init_kernel(float4* __restrict__ out) {
    int i = blockIdx.x * 256 + threadIdx.x;
    if (i < NV*Uc/4)    out[i] = make_float4(0.f, 0.f, 0.f, 0.f);
    if (i < NV*SLOTS/4) ((int4*)g_winner)[i] = make_int4(-1, -1, -1, -1);
    if (i < 3*2048) {   // pad rows Ec..EP of each type, 32 rows x 64 words
        int tt = i >> 11;
        int w  = i & 2047;
        size_t off = ((size_t)tt*EP + Ec)*64 + w;
        g_Ahi[off] = 0;
        g_Alo[off] = 0;
    }
}

// ---------------------------------------------------------------------------
// K1: fdot[bv] = features[bv]·W_att[0:128] + b_att
// ---------------------------------------------------------------------------
__global__ void fdot_kernel(const float* __restrict__ feat,
                            const float* __restrict__ Wa,
                            const float* __restrict__ ba) {
    int w = (blockIdx.x * blockDim.x + threadIdx.x) >> 5;
    int lane = threadIdx.x & 31;
    if (w >= NV) return;
    const float4 f = ((const float4*)(feat + (size_t)w * Fc))[lane];
    const float4 a = __ldg(((const float4*)Wa) + lane);
    float s = f.x*a.x + f.y*a.y + f.z*a.z + f.w*a.w;
#pragma unroll
    for (int o = 16; o; o >>= 1) s += __shfl_xor_sync(0xffffffffu, s, o);
    if (lane == 0) g_fdot[w] = s + ba[0];
}

// ---------------------------------------------------------------------------
// K1b: w̃, cterm, and W^T bf16 hi/lo split pair images (unpadded)
// ---------------------------------------------------------------------------
__global__ void prep_kernel(const float* __restrict__ Wd,
                            const float* __restrict__ bd,
                            const float* __restrict__ Wa) {
    int t = blockIdx.x;
    int tid = threadIdx.x;   // 256
    if (tid < 128) {
        const float* row = Wd + ((size_t)t * 128 + tid) * 128;
        float s = 0.f;
#pragma unroll 8
        for (int u = 0; u < 128; u++) s += row[u] * __ldg(&Wa[128 + u]);
        g_wtilde[t * 128 + tid] = s;
        if (tid == 0) {
            float cb = 0.f;
            for (int u = 0; u < 128; u++) cb += bd[t * 128 + u] * Wa[128 + u];
            g_cterm[t] = cb;
        }
    }
    for (int i = tid; i < 128 * 64; i += 256) {
        int n  = i >> 6;       // output col (N dim)
        int kp = i & 63;       // k pair
        float w0 = Wd[(size_t)t * 16384 + (size_t)(2*kp)     * 128 + n];
        float w1 = Wd[(size_t)t * 16384 + (size_t)(2*kp + 1) * 128 + n];
        uint32_t hp, lp;
        split2(w0, w1, hp, lp);
        g_Whi[(size_t)t * 8192 + n * 64 + kp] = hp;
        g_Wlo[(size_t)t * 8192 + n * 64 + kp] = lp;
    }
}

// ---------------------------------------------------------------------------
// K2: logits (4 edges/warp) + bf16 hi/lo split emission (row-major, EP stride)
// ---------------------------------------------------------------------------
__global__ void logits_kernel(const float* __restrict__ ef,
                              const int*   __restrict__ eidx) {
    int wg = (blockIdx.x * 256 + threadIdx.x) >> 5;
    int lane = threadIdx.x & 31;
    if (wg >= Tc * (Ec/4)) return;
    int t = wg / (Ec/4);
    int e0 = (wg - t * (Ec/4)) * 4;
    const float4* base = (const float4*)(ef + ((size_t)t * Ec + e0) * 128);
    float4 a0 = base[lane];
    float4 a1 = base[32 + lane];
    float4 a2 = base[64 + lane];
    float4 a3 = base[96 + lane];
    const float4 w = __ldg(((const float4*)(g_wtilde + t * 128)) + lane);
    float s0 = a0.x*w.x + a0.y*w.y + a0.z*w.z + a0.w*w.w;
    float s1 = a1.x*w.x + a1.y*w.y + a1.z*w.z + a1.w*w.w;
    float s2 = a2.x*w.x + a2.y*w.y + a2.z*w.z + a2.w*w.w;
    float s3 = a3.x*w.x + a3.y*w.y + a3.z*w.z + a3.w*w.w;

    // emit bf16 hi/lo split (row-major, 64 words per row, EP stride)
    {
        float4 rows[4] = {a0, a1, a2, a3};
#pragma unroll
        for (int j = 0; j < 4; j++) {
            uint32_t h0, l0, h1, l1;
            split2(rows[j].x, rows[j].y, h0, l0);
            split2(rows[j].z, rows[j].w, h1, l1);
            size_t off = ((size_t)t*EP + e0 + j)*64 + 2*lane;
            *(uint2*)&g_Ahi[off] = make_uint2(h0, h1);
            *(uint2*)&g_Alo[off] = make_uint2(l0, l1);
        }
    }

#pragma unroll
    for (int o = 16; o; o >>= 1) {
        s0 += __shfl_xor_sync(0xffffffffu, s0, o);
        s1 += __shfl_xor_sync(0xffffffffu, s1, o);
        s2 += __shfl_xor_sync(0xffffffffu, s2, o);
        s3 += __shfl_xor_sync(0xffffffffu, s3, o);
    }
    if (lane < 4) {
        float sv = (lane == 0) ? s0 : (lane == 1) ? s1 : (lane == 2) ? s2 : s3;
        int e = e0 + lane;
        const int* ei = eidx + ((size_t)t * Ec + e) * 3;
        int b = ei[0], v = ei[1], sl = ei[2];
        int bv = b * Vc + v;
        float x = g_fdot[bv] + sv + g_cterm[t];
        float logit = (x > 0.0f) ? x : 0.3f * x;
        g_logits[t * Ec + e] = logit;
        atomicMax(&g_winner[bv * SLOTS + t * Nc + sl], e);
    }
}

// ---------------------------------------------------------------------------
// K3: per-vertex softmax stats
// ---------------------------------------------------------------------------
__global__ void vertex_kernel(const int* __restrict__ adj) {
    int vert = (blockIdx.x * blockDim.x + threadIdx.x) >> 5;
    int lane = threadIdx.x & 31;
    if (vert >= NV) return;
    const int base = vert * SLOTS;
    float l[3];
    int deg = 0;
#pragma unroll
    for (int i = 0; i < 3; i++) {
        int slot = i * 32 + lane;
        int w = g_winner[base + slot];
        deg += (adj[base + slot] >= 0) ? 1 : 0;
        l[i] = (w >= 0) ? g_logits[i * Ec + w] : -200.0f;
    }
    float m = fmaxf(fmaxf(l[0], l[1]), l[2]);
#pragma unroll
    for (int o = 16; o; o >>= 1) m = fmaxf(m, __shfl_xor_sync(0xffffffffu, m, o));
    float den = expf(l[0] - m) + expf(l[1] - m) + expf(l[2] - m);
#pragma unroll
    for (int o = 16; o; o >>= 1) {
        den += __shfl_xor_sync(0xffffffffu, den, o);
        deg += __shfl_xor_sync(0xffffffffu, deg, o);
    }
    if (lane == 0) { g_m[vert] = m; g_c[vert] = (float)deg / den; }
}

// ---------------------------------------------------------------------------
// K4: bf16x3 split HMMA GEMM, cp.async pipeline, fused weighted scatter.
// SMEM (bytes): W_hi [0,32768) + W_lo [32768,65536), both xor-swizzled
//   (granule' = g ^ (n&7)); A: 3 bufs x 16384 at 65536 (hi 8KB + lo 8KB each,
//   granule' = g ^ ((row>>1)&3)); satt/sbv overlaid in buf2 (dead between
//   MMA(2) and next-tile prologue).
// ---------------------------------------------------------------------------
#define WHI_OFF 0
#define WLO_OFF 32768
#define ABUF_OFF 65536
#define SATT_OFF (ABUF_OFF + 2*16384)
#define SBV_OFF  (SATT_OFF + 512)
#define SMEM_BYTES (ABUF_OFF + 3*16384)   // 114688

__global__ __launch_bounds__(256, 2)
void gemm_hmma(const float* __restrict__ bd,    // [T,128]
               const int*   __restrict__ eidx,  // [T,E,3]
               float* __restrict__ out)
{
    extern __shared__ uint32_t sm[];
    char* smc = (char*)sm;
    const int tid  = threadIdx.x;
    const int lane = tid & 31;
    const int wid  = tid >> 5;
    const int wm   = wid >> 2;          // 0..1 : row-block of 64
    const int wn   = wid & 3;           // 0..3 : col-block of 32
    const int gi   = lane >> 2;         // 0..7
    const int m4   = lane >> 3;         // ldmatrix matrix idx
    const int lr   = lane & 7;
    const int t    = blockIdx.y;

    // --- prologue: W hi/lo into smem with xor swizzle; bias into regs
    {
        const uint4* gwh = (const uint4*)(g_Whi + (size_t)t*8192);
        const uint4* gwl = (const uint4*)(g_Wlo + (size_t)t*8192);
        uint4* swh = (uint4*)(smc + WHI_OFF);
        uint4* swl = (uint4*)(smc + WLO_OFF);
        for (int idx = tid; idx < 2048; idx += 256) {
            int n = idx >> 4, g = idx & 15;
            int d = n*16 + (g ^ (n & 7));
            swh[d] = gwh[idx];
            swl[d] = gwl[idx];
        }
    }
    float biasr[8];
#pragma unroll
    for (int nf = 0; nf < 4; nf++) {
        biasr[nf*2]   = bd[t*128 + wn*32 + nf*8 + (lane&3)*2];
        biasr[nf*2+1] = bd[t*128 + wn*32 + nf*8 + (lane&3)*2 + 1];
    }
    __syncthreads();

    float* satt = (float*)(smc + SATT_OFF);
    int*   sbv  = (int*)(smc + SBV_OFF);
    const uint32_t smb = smem_u32(sm);

    // ldmatrix per-lane constants
    const uint32_t wbase  = smb + WHI_OFF + (uint32_t)(wn*32 + (m4>>1)*8 + lr) * 256;
    const uint32_t gbitB  = (uint32_t)(m4 & 1);
    const uint32_t abase0 = smb + ABUF_OFF + (uint32_t)(wm*64 + (m4&1)*8 + lr) * 64;
    const uint32_t ga2    = (uint32_t)(m4 >> 1);
    const uint32_t sA     = (uint32_t)((lr >> 1) & 3);

    // cp.async per-thread indices: 2 hi + 2 lo granules per chunk
    const int rcp = tid >> 1;                 // 0..127
    const int gcp = (tid & 1) * 2;            // 0 or 2
    const uint32_t sAcp = (uint32_t)((rcp >> 1) & 3);

    for (int tile = blockIdx.x; tile < NT; tile += GRIDX) {
        const int e0 = tile * 128;
        const int rowsv = min(128, Ec - e0);

        // --- att prefetch (long-latency chain overlapped with whole tile)
        float attR = 0.f; int bvR = 0;
        if (tid < 128 && tid < rowsv) {
            int e = e0 + tid;
            const int* ei = eidx + ((size_t)t * Ec + e) * 3;
            int b = ei[0], v = ei[1], sl = ei[2];
            int bv = b * Vc + v;
            int w = g_winner[bv * SLOTS + t * Nc + sl];
            attR = expf(g_logits[t * Ec + w] - g_m[bv]) * g_c[bv];
            bvR = bv;
        }

        const char* srcBh = (const char*)g_Ahi + (((size_t)t*EP + e0 + rcp)*64)*4;
        const char* srcBl = (const char*)g_Alo + (((size_t)t*EP + e0 + rcp)*64)*4;
        const uint32_t dstBase = smb + ABUF_OFF + (uint32_t)rcp*64;

        #define COPY_A(c) do { \
            uint32_t _dst = dstBase + (uint32_t)(((c)%3)*16384); \
            const char* _sh = srcBh + (c)*64; \
            const char* _sl = srcBl + (c)*64; \
            _Pragma("unroll") \
            for (int q = 0; q < 2; q++) { \
                int _g = gcp + q; \
                uint32_t _sw = (uint32_t)((_g ^ sAcp) << 4); \
                cpa16(_dst + _sw, _sh + _g*16); \
                cpa16(_dst + 8192 + _sw, _sl + _g*16); \
            } \
            CP_COMMIT(); \
        } while (0)

        float4 acc[4][4];
#pragma unroll
        for (int i = 0; i < 4; i++)
#pragma unroll
            for (int j = 0; j < 4; j++) acc[i][j] = make_float4(0.f,0.f,0.f,0.f);

        COPY_A(0);
        COPY_A(1);
        COPY_A(2);

        #define DO_CHUNK(c, WN, DOCOPY3) do { \
            asm volatile("cp.async.wait_group %0;" :: "n"(WN) : "memory"); \
            __syncthreads(); \
            const uint32_t abuf = abase0 + (uint32_t)(((c)%3)*16384); \
            _Pragma("unroll") \
            for (int kk = 0; kk < 2; kk++) { \
                uint32_t bA = wbase + ((((uint32_t)(c)*4u + (uint32_t)kk*2u + gbitB) ^ (uint32_t)lr) << 4); \
                uint32_t bh[8], bl[8]; \
                ldsm4(bh[0],bh[1],bh[2],bh[3], bA); \
                ldsm4(bh[4],bh[5],bh[6],bh[7], bA + 4096); \
                ldsm4(bl[0],bl[1],bl[2],bl[3], bA + 32768); \
                ldsm4(bl[4],bl[5],bl[6],bl[7], bA + 32768 + 4096); \
                uint32_t gsw = ((((uint32_t)kk*2u + ga2) ^ sA) << 4); \
                _Pragma("unroll") \
                for (int mf = 0; mf < 4; mf++) { \
                    uint32_t aaddr = abuf + (uint32_t)mf*1024 + gsw; \
                    uint32_t ah[4], al[4]; \
                    ldsm4(ah[0],ah[1],ah[2],ah[3], aaddr); \
                    ldsm4(al[0],al[1],al[2],al[3], aaddr + 8192); \
                    _Pragma("unroll") \
                    for (int nf = 0; nf < 4; nf++) \
                        mma16816(acc[mf][nf], ah[0], ah[1], ah[2], ah[3], bh[2*nf], bh[2*nf+1]); \
                    _Pragma("unroll") \
                    for (int nf = 0; nf < 4; nf++) \
                        mma16816(acc[mf][nf], ah[0], ah[1], ah[2], ah[3], bl[2*nf], bl[2*nf+1]); \
                    _Pragma("unroll") \
                    for (int nf = 0; nf < 4; nf++) \
                        mma16816(acc[mf][nf], al[0], al[1], al[2], al[3], bh[2*nf], bh[2*nf+1]); \
                } \
            } \
            if (DOCOPY3) COPY_A(3); \
        } while (0)

        DO_CHUNK(0, 2, 0);
        DO_CHUNK(1, 1, 1);   // copy(3) here: all warps past sync(1) => MMA(0) done
        DO_CHUNK(2, 1, 0);
        DO_CHUNK(3, 0, 0);

        // --- epilogue: publish att/bv (buf2 region is dead now), then RED
        if (tid < 128) { satt[tid] = attR; sbv[tid] = bvR; }
        __syncthreads();

#pragma unroll
        for (int mf = 0; mf < 4; mf++) {
            int r0 = wm*64 + mf*16 + gi;
            int r1 = r0 + 8;
            float a0 = satt[r0], a1 = satt[r1];
            size_t o0 = (size_t)sbv[r0] * 128, o1 = (size_t)sbv[r1] * 128;
#pragma unroll
            for (int nf = 0; nf < 4; nf++) {
                int col = wn*32 + nf*8 + (lane & 3)*2;
                float4 ac = acc[mf][nf];
                red2(out + o0 + col, (ac.x + biasr[nf*2]) * a0, (ac.y + biasr[nf*2+1]) * a0);
                red2(out + o1 + col, (ac.z + biasr[nf*2]) * a1, (ac.w + biasr[nf*2+1]) * a1);
            }
        }
        __syncthreads();   // protects satt/sbv + buffers before next tile's copies
        #undef DO_CHUNK
        #undef COPY_A
    }
}

// ---------------------------------------------------------------------------
extern "C" void kernel_launch(void* const* d_in, const int* in_sizes, int n_in,
                              void* d_out, int out_size) {
    const int*   adjacency  = (const int*)  d_in[0];
    const float* features   = (const float*)d_in[1];
    const int*   edge_idxs  = (const int*)  d_in[2];
    const float* edge_feats = (const float*)d_in[3];
    const float* W_dense    = (const float*)d_in[4];
    const float* b_dense    = (const float*)d_in[5];
    const float* W_att      = (const float*)d_in[6];
    const float* b_att      = (const float*)d_in[7];
    float* out = (float*)d_out;

    cudaFuncSetAttribute(gemm_hmma,
                         cudaFuncAttributeMaxDynamicSharedMemorySize, SMEM_BYTES);

    init_kernel<<<(NV*Uc/4 + 255)/256, 256>>>((float4*)out);
    fdot_kernel<<<(NV*32 + 255)/256, 256>>>(features, W_att, b_att);
    prep_kernel<<<Tc, 256>>>(W_dense, b_dense, W_att);
    logits_kernel<<<(Tc*(Ec/4)*32 + 255)/256, 256>>>(edge_feats, edge_idxs);
    vertex_kernel<<<(NV*32 + 255)/256, 256>>>(adjacency);
    dim3 gg(GRIDX, 3);
    gemm_hmma<<<gg, 256, SMEM_BYTES>>>(b_dense, edge_idxs, out);
}

// round 15
// speedup vs baseline: 2.1053x; 1.2391x over previous
#include <cuda_runtime.h>
#include <cuda_fp16.h>
#include <math.h>
#include <stdint.h>

// Problem constants (fixed by setup_inputs)
#define Bc 2
#define Vc 50000
#define Tc 3
#define Nc 32
#define Fc 128
#define Uc 128
#define Ec 300000
#define NV (Bc*Vc)          // 100000 vertices
#define SLOTS (Tc*Nc)       // 96 slots per vertex
#define NT ((Ec + 127) / 128)   // 2344 tiles per type
#define EP (NT*128)             // 300032 padded edge stride
#define GRIDX 296

// ---------------------------------------------------------------------------
// Device scratch (no allocation allowed)
// ---------------------------------------------------------------------------
__device__ float    g_logits[Tc*Ec];
__device__ int      g_winner[NV*SLOTS];
__device__ float    g_m[NV];
__device__ float    g_c[NV];
__device__ float    g_fdot[NV];
__device__ float    g_wtilde[Tc*Fc];       // W_t @ W_att[128:]
__device__ float    g_cterm[Tc];           // b_t · W_att[128:]
__device__ uint32_t g_Wh[Tc*128*64];       // W^T hi fp16-pairs, [n][kpair]
__device__ uint32_t g_Wl[Tc*128*64];       // W^T lo fp16-pairs
__device__ uint32_t g_Ah[(size_t)Tc*EP*64];// ef fp16-pairs (single term), row-major

// ---------------------------------------------------------------------------
// Helpers
// ---------------------------------------------------------------------------
__device__ __forceinline__ uint32_t packh2(float x, float y) {
    __half2 h = __floats2half2_rn(x, y);
    return *reinterpret_cast<uint32_t*>(&h);
}
__device__ __forceinline__ void splitH2(float x, float y, uint32_t& hp, uint32_t& lp) {
    __half2 h = __floats2half2_rn(x, y);
    float hx = __low2float(h);
    float hy = __high2float(h);
    __half2 l = __floats2half2_rn(x - hx, y - hy);
    hp = *reinterpret_cast<uint32_t*>(&h);
    lp = *reinterpret_cast<uint32_t*>(&l);
}

__device__ __forceinline__ void mma16816(float4& d,
        uint32_t a0, uint32_t a1, uint32_t a2, uint32_t a3,
        uint32_t b0, uint32_t b1) {
    asm volatile("mma.sync.aligned.m16n8k16.row.col.f32.f16.f16.f32 "
        "{%0,%1,%2,%3}, {%4,%5,%6,%7}, {%8,%9}, {%0,%1,%2,%3};"
        : "+f"(d.x), "+f"(d.y), "+f"(d.z), "+f"(d.w)
        : "r"(a0), "r"(a1), "r"(a2), "r"(a3), "r"(b0), "r"(b1));
}

__device__ __forceinline__ void ldsm4(uint32_t& r0, uint32_t& r1,
                                      uint32_t& r2, uint32_t& r3, uint32_t addr) {
    asm volatile("ldmatrix.sync.aligned.m8n8.x4.shared.b16 {%0,%1,%2,%3}, [%4];"
        : "=r"(r0), "=r"(r1), "=r"(r2), "=r"(r3) : "r"(addr));
}

__device__ __forceinline__ void red2(float* p, float x, float y) {
    asm volatile("red.global.add.v2.f32 [%0], {%1, %2};" :: "l"(p), "f"(x), "f"(y) : "memory");
}

__device__ __forceinline__ uint32_t smem_u32(const void* p) {
    uint32_t a;
    asm("{ .reg .u64 t; cvta.to.shared.u64 t, %1; cvt.u32.u64 %0, t; }" : "=r"(a) : "l"(p));
    return a;
}

__device__ __forceinline__ void cpa16(uint32_t dst, const void* src) {
    asm volatile("cp.async.cg.shared.global [%0], [%1], 16;" :: "r"(dst), "l"(src) : "memory");
}
#define CP_COMMIT() asm volatile("cp.async.commit_group;" ::: "memory")

// ---------------------------------------------------------------------------
// K0: init winner grid to -1, out to 0, zero A pad rows
// ---------------------------------------------------------------------------
__global__ void init_kernel(float4* __restrict__ out) {
    int i = blockIdx.x * 256 + threadIdx.x;
    if (i < NV*Uc/4)    out[i] = make_float4(0.f, 0.f, 0.f, 0.f);
    if (i < NV*SLOTS/4) ((int4*)g_winner)[i] = make_int4(-1, -1, -1, -1);
    if (i < 3*2048) {   // pad rows Ec..EP of each type, 32 rows x 64 words
        int tt = i >> 11;
        int w  = i & 2047;
        g_Ah[((size_t)tt*EP + Ec)*64 + w] = 0;
    }
}

// ---------------------------------------------------------------------------
// K1: fdot[bv] = features[bv]·W_att[0:128] + b_att
// ---------------------------------------------------------------------------
__global__ void fdot_kernel(const float* __restrict__ feat,
                            const float* __restrict__ Wa,
                            const float* __restrict__ ba) {
    int w = (blockIdx.x * blockDim.x + threadIdx.x) >> 5;
    int lane = threadIdx.x & 31;
    if (w >= NV) return;
    const float4 f = ((const float4*)(feat + (size_t)w * Fc))[lane];
    const float4 a = __ldg(((const float4*)Wa) + lane);
    float s = f.x*a.x + f.y*a.y + f.z*a.z + f.w*a.w;
#pragma unroll
    for (int o = 16; o; o >>= 1) s += __shfl_xor_sync(0xffffffffu, s, o);
    if (lane == 0) g_fdot[w] = s + ba[0];
}

// ---------------------------------------------------------------------------
// K1b: w̃, cterm, and W^T fp16 hi/lo split pair images (unpadded)
// ---------------------------------------------------------------------------
__global__ void prep_kernel(const float* __restrict__ Wd,
                            const float* __restrict__ bd,
                            const float* __restrict__ Wa) {
    int t = blockIdx.x;
    int tid = threadIdx.x;   // 256
    if (tid < 128) {
        const float* row = Wd + ((size_t)t * 128 + tid) * 128;
        float s = 0.f;
#pragma unroll 8
        for (int u = 0; u < 128; u++) s += row[u] * __ldg(&Wa[128 + u]);
        g_wtilde[t * 128 + tid] = s;
        if (tid == 0) {
            float cb = 0.f;
            for (int u = 0; u < 128; u++) cb += bd[t * 128 + u] * Wa[128 + u];
            g_cterm[t] = cb;
        }
    }
    for (int i = tid; i < 128 * 64; i += 256) {
        int n  = i >> 6;       // output col (N dim)
        int kp = i & 63;       // k pair
        float w0 = Wd[(size_t)t * 16384 + (size_t)(2*kp)     * 128 + n];
        float w1 = Wd[(size_t)t * 16384 + (size_t)(2*kp + 1) * 128 + n];
        uint32_t hp, lp;
        splitH2(w0, w1, hp, lp);
        g_Wh[(size_t)t * 8192 + n * 64 + kp] = hp;
        g_Wl[(size_t)t * 8192 + n * 64 + kp] = lp;
    }
}

// ---------------------------------------------------------------------------
// K2: logits (4 edges/warp) + single-term fp16 A emission (row-major, EP stride)
// ---------------------------------------------------------------------------
__global__ void logits_kernel(const float* __restrict__ ef,
                              const int*   __restrict__ eidx) {
    int wg = (blockIdx.x * 256 + threadIdx.x) >> 5;
    int lane = threadIdx.x & 31;
    if (wg >= Tc * (Ec/4)) return;
    int t = wg / (Ec/4);
    int e0 = (wg - t * (Ec/4)) * 4;
    const float4* base = (const float4*)(ef + ((size_t)t * Ec + e0) * 128);
    float4 a0 = base[lane];
    float4 a1 = base[32 + lane];
    float4 a2 = base[64 + lane];
    float4 a3 = base[96 + lane];
    const float4 w = __ldg(((const float4*)(g_wtilde + t * 128)) + lane);
    float s0 = a0.x*w.x + a0.y*w.y + a0.z*w.z + a0.w*w.w;
    float s1 = a1.x*w.x + a1.y*w.y + a1.z*w.z + a1.w*w.w;
    float s2 = a2.x*w.x + a2.y*w.y + a2.z*w.z + a2.w*w.w;
    float s3 = a3.x*w.x + a3.y*w.y + a3.z*w.z + a3.w*w.w;

    // emit fp16 A (single term), 64 words per row, EP stride
    {
        float4 rows[4] = {a0, a1, a2, a3};
#pragma unroll
        for (int j = 0; j < 4; j++) {
            size_t off = ((size_t)t*EP + e0 + j)*64 + 2*lane;
            *(uint2*)&g_Ah[off] = make_uint2(packh2(rows[j].x, rows[j].y),
                                             packh2(rows[j].z, rows[j].w));
        }
    }

#pragma unroll
    for (int o = 16; o; o >>= 1) {
        s0 += __shfl_xor_sync(0xffffffffu, s0, o);
        s1 += __shfl_xor_sync(0xffffffffu, s1, o);
        s2 += __shfl_xor_sync(0xffffffffu, s2, o);
        s3 += __shfl_xor_sync(0xffffffffu, s3, o);
    }
    if (lane < 4) {
        float sv = (lane == 0) ? s0 : (lane == 1) ? s1 : (lane == 2) ? s2 : s3;
        int e = e0 + lane;
        const int* ei = eidx + ((size_t)t * Ec + e) * 3;
        int b = ei[0], v = ei[1], sl = ei[2];
        int bv = b * Vc + v;
        float x = g_fdot[bv] + sv + g_cterm[t];
        float logit = (x > 0.0f) ? x : 0.3f * x;
        g_logits[t * Ec + e] = logit;
        atomicMax(&g_winner[bv * SLOTS + t * Nc + sl], e);
    }
}

// ---------------------------------------------------------------------------
// K3: per-vertex softmax stats
// ---------------------------------------------------------------------------
__global__ void vertex_kernel(const int* __restrict__ adj) {
    int vert = (blockIdx.x * blockDim.x + threadIdx.x) >> 5;
    int lane = threadIdx.x & 31;
    if (vert >= NV) return;
    const int base = vert * SLOTS;
    float l[3];
    int deg = 0;
#pragma unroll
    for (int i = 0; i < 3; i++) {
        int slot = i * 32 + lane;
        int w = g_winner[base + slot];
        deg += (adj[base + slot] >= 0) ? 1 : 0;
        l[i] = (w >= 0) ? g_logits[i * Ec + w] : -200.0f;
    }
    float m = fmaxf(fmaxf(l[0], l[1]), l[2]);
#pragma unroll
    for (int o = 16; o; o >>= 1) m = fmaxf(m, __shfl_xor_sync(0xffffffffu, m, o));
    float den = expf(l[0] - m) + expf(l[1] - m) + expf(l[2] - m);
#pragma unroll
    for (int o = 16; o; o >>= 1) {
        den += __shfl_xor_sync(0xffffffffu, den, o);
        deg += __shfl_xor_sync(0xffffffffu, deg, o);
    }
    if (lane == 0) { g_m[vert] = m; g_c[vert] = (float)deg / den; }
}

// ---------------------------------------------------------------------------
// K4: fp16 2-MMA GEMM (A single, W hi+lo), cp.async pipeline, fused scatter.
// SMEM (bytes): W_hi [0,32768), W_lo [32768,65536), xor-swizzled (g' = g^(n&7));
//   A: 3 bufs x 8192 at 65536, g' = g ^ ((row>>1)&3); satt/sbv after buffers.
// ---------------------------------------------------------------------------
#define WHI_OFF 0
#define WLO_OFF 32768
#define ABUF_OFF 65536
#define SATT_OFF (ABUF_OFF + 3*8192)
#define SBV_OFF  (SATT_OFF + 512)
#define SMEM_BYTES (SBV_OFF + 512)   // 91648

__global__ __launch_bounds__(256, 2)
void gemm_hmma(const float* __restrict__ bd,    // [T,128]
               const int*   __restrict__ eidx,  // [T,E,3]
               float* __restrict__ out)
{
    extern __shared__ uint32_t sm[];
    char* smc = (char*)sm;
    const int tid  = threadIdx.x;
    const int lane = tid & 31;
    const int wid  = tid >> 5;
    const int wm   = wid >> 2;          // 0..1 : row-block of 64
    const int wn   = wid & 3;           // 0..3 : col-block of 32
    const int gi   = lane >> 2;         // 0..7
    const int m4   = lane >> 3;         // ldmatrix matrix idx
    const int lr   = lane & 7;
    const int t    = blockIdx.y;

    // --- prologue: W hi/lo into smem with xor swizzle; bias into regs
    {
        const uint4* gwh = (const uint4*)(g_Wh + (size_t)t*8192);
        const uint4* gwl = (const uint4*)(g_Wl + (size_t)t*8192);
        uint4* swh = (uint4*)(smc + WHI_OFF);
        uint4* swl = (uint4*)(smc + WLO_OFF);
        for (int idx = tid; idx < 2048; idx += 256) {
            int n = idx >> 4, g = idx & 15;
            int d = n*16 + (g ^ (n & 7));
            swh[d] = gwh[idx];
            swl[d] = gwl[idx];
        }
    }
    float biasr[8];
#pragma unroll
    for (int nf = 0; nf < 4; nf++) {
        biasr[nf*2]   = bd[t*128 + wn*32 + nf*8 + (lane&3)*2];
        biasr[nf*2+1] = bd[t*128 + wn*32 + nf*8 + (lane&3)*2 + 1];
    }
    __syncthreads();

    float* satt = (float*)(smc + SATT_OFF);
    int*   sbv  = (int*)(smc + SBV_OFF);
    const uint32_t smb = smem_u32(sm);

    // ldmatrix per-lane constants
    const uint32_t wbase  = smb + WHI_OFF + (uint32_t)(wn*32 + (m4>>1)*8 + lr) * 256;
    const uint32_t gbitB  = (uint32_t)(m4 & 1);
    const uint32_t abase0 = smb + ABUF_OFF + (uint32_t)(wm*64 + (m4&1)*8 + lr) * 64;
    const uint32_t ga2    = (uint32_t)(m4 >> 1);
    const uint32_t sA     = (uint32_t)((lr >> 1) & 3);

    // cp.async per-thread indices: 2 granules per chunk
    const int rcp = tid >> 1;                 // 0..127
    const int gcp = (tid & 1) * 2;            // 0 or 2
    const uint32_t sAcp = (uint32_t)((rcp >> 1) & 3);

    for (int tile = blockIdx.x; tile < NT; tile += GRIDX) {
        const int e0 = tile * 128;
        const int rowsv = min(128, Ec - e0);

        // --- att prefetch (long-latency chain overlapped with whole tile)
        float attR = 0.f; int bvR = 0;
        if (tid < 128 && tid < rowsv) {
            int e = e0 + tid;
            const int* ei = eidx + ((size_t)t * Ec + e) * 3;
            int b = ei[0], v = ei[1], sl = ei[2];
            int bv = b * Vc + v;
            int w = g_winner[bv * SLOTS + t * Nc + sl];
            attR = expf(g_logits[t * Ec + w] - g_m[bv]) * g_c[bv];
            bvR = bv;
        }

        const char* srcA = (const char*)g_Ah + ((size_t)t*EP + e0 + rcp)*256;
        const uint32_t dstBase = smb + ABUF_OFF + (uint32_t)rcp*64;

        #define COPY_A(c) do { \
            uint32_t _dst = dstBase + (uint32_t)(((c)%3)*8192); \
            const char* _s = srcA + (c)*64; \
            _Pragma("unroll") \
            for (int q = 0; q < 2; q++) { \
                int _g = gcp + q; \
                uint32_t _sw = (uint32_t)((_g ^ sAcp) << 4); \
                cpa16(_dst + _sw, _s + _g*16); \
            } \
            CP_COMMIT(); \
        } while (0)

        float4 acc[4][4];
#pragma unroll
        for (int i = 0; i < 4; i++)
#pragma unroll
            for (int j = 0; j < 4; j++) acc[i][j] = make_float4(0.f,0.f,0.f,0.f);

        COPY_A(0);
        COPY_A(1);
        COPY_A(2);

        #define DO_CHUNK(c, WN, DOCOPY3) do { \
            asm volatile("cp.async.wait_group %0;" :: "n"(WN) : "memory"); \
            __syncthreads(); \
            const uint32_t abuf = abase0 + (uint32_t)(((c)%3)*8192); \
            _Pragma("unroll") \
            for (int kk = 0; kk < 2; kk++) { \
                uint32_t bA = wbase + ((((uint32_t)(c)*4u + (uint32_t)kk*2u + gbitB) ^ (uint32_t)lr) << 4); \
                uint32_t bh[8], bl[8]; \
                ldsm4(bh[0],bh[1],bh[2],bh[3], bA); \
                ldsm4(bh[4],bh[5],bh[6],bh[7], bA + 4096); \
                ldsm4(bl[0],bl[1],bl[2],bl[3], bA + 32768); \
                ldsm4(bl[4],bl[5],bl[6],bl[7], bA + 32768 + 4096); \
                uint32_t gsw = ((((uint32_t)kk*2u + ga2) ^ sA) << 4); \
                _Pragma("unroll") \
                for (int mf = 0; mf < 4; mf++) { \
                    uint32_t aaddr = abuf + (uint32_t)mf*1024 + gsw; \
                    uint32_t ah[4]; \
                    ldsm4(ah[0],ah[1],ah[2],ah[3], aaddr); \
                    _Pragma("unroll") \
                    for (int nf = 0; nf < 4; nf++) \
                        mma16816(acc[mf][nf], ah[0], ah[1], ah[2], ah[3], bh[2*nf], bh[2*nf+1]); \
                    _Pragma("unroll") \
                    for (int nf = 0; nf < 4; nf++) \
                        mma16816(acc[mf][nf], ah[0], ah[1], ah[2], ah[3], bl[2*nf], bl[2*nf+1]); \
                } \
            } \
            if (DOCOPY3) COPY_A(3); \
        } while (0)

        DO_CHUNK(0, 2, 0);
        DO_CHUNK(1, 1, 1);   // copy(3) here: all warps past sync(1) => MMA(0) done
        DO_CHUNK(2, 1, 0);
        DO_CHUNK(3, 0, 0);

        // --- epilogue: publish att/bv, then RED
        if (tid < 128) { satt[tid] = attR; sbv[tid] = bvR; }
        __syncthreads();

#pragma unroll
        for (int mf = 0; mf < 4; mf++) {
            int r0 = wm*64 + mf*16 + gi;
            int r1 = r0 + 8;
            float a0 = satt[r0], a1 = satt[r1];
            size_t o0 = (size_t)sbv[r0] * 128, o1 = (size_t)sbv[r1] * 128;
#pragma unroll
            for (int nf = 0; nf < 4; nf++) {
                int col = wn*32 + nf*8 + (lane & 3)*2;
                float4 ac = acc[mf][nf];
                red2(out + o0 + col, (ac.x + biasr[nf*2]) * a0, (ac.y + biasr[nf*2+1]) * a0);
                red2(out + o1 + col, (ac.z + biasr[nf*2]) * a1, (ac.w + biasr[nf*2+1]) * a1);
            }
        }
        __syncthreads();   // protects satt/sbv + buffers before next tile's copies
        #undef DO_CHUNK
        #undef COPY_A
    }
}

// ---------------------------------------------------------------------------
extern "C" void kernel_launch(void* const* d_in, const int* in_sizes, int n_in,
                              void* d_out, int out_size) {
    const int*   adjacency  = (const int*)  d_in[0];
    const float* features   = (const float*)d_in[1];
    const int*   edge_idxs  = (const int*)  d_in[2];
    const float* edge_feats = (const float*)d_in[3];
    const float* W_dense    = (const float*)d_in[4];
    const float* b_dense    = (const float*)d_in[5];
    const float* W_att      = (const float*)d_in[6];
    const float* b_att      = (const float*)d_in[7];
    float* out = (float*)d_out;

    cudaFuncSetAttribute(gemm_hmma,
                         cudaFuncAttributeMaxDynamicSharedMemorySize, SMEM_BYTES);

    init_kernel<<<(NV*Uc/4 + 255)/256, 256>>>((float4*)out);
    fdot_kernel<<<(NV*32 + 255)/256, 256>>>(features, W_att, b_att);
    prep_kernel<<<Tc, 256>>>(W_dense, b_dense, W_att);
    logits_kernel<<<(Tc*(Ec/4)*32 + 255)/256, 256>>>(edge_feats, edge_idxs);
    vertex_kernel<<<(NV*32 + 255)/256, 256>>>(adjacency);
    dim3 gg(GRIDX, 3);
    gemm_hmma<<<gg, 256, SMEM_BYTES>>>(b_dense, edge_idxs, out);
}

// round 16
// speedup vs baseline: 2.3079x; 1.0963x over previous
#include <cuda_runtime.h>
#include <cuda_fp16.h>
#include <math.h>
#include <stdint.h>

// Problem constants (fixed by setup_inputs)
#define Bc 2
#define Vc 50000
#define Tc 3
#define Nc 32
#define Fc 128
#define Uc 128
#define Ec 300000
#define NV (Bc*Vc)          // 100000 vertices
#define SLOTS (Tc*Nc)       // 96 slots per vertex
#define NT ((Ec + 127) / 128)   // 2344 tiles per type
#define EP (NT*128)             // 300032 padded edge stride
#define GRIDX 296

// ---------------------------------------------------------------------------
// Device scratch (no allocation allowed)
// ---------------------------------------------------------------------------
__device__ float    g_logits[Tc*Ec];
__device__ int      g_winner[NV*SLOTS];
__device__ float    g_m[NV];
__device__ float    g_c[NV];
__device__ float    g_fdot[NV];
__device__ float    g_wtilde[Tc*Fc];       // W_t @ W_att[128:]
__device__ float    g_cterm[Tc];           // b_t · W_att[128:]
__device__ uint32_t g_Wh[Tc*128*64];       // W^T fp16-pairs, [n][kpair]
__device__ uint32_t g_Ah[(size_t)Tc*EP*64];// ef fp16-pairs, row-major

// ---------------------------------------------------------------------------
// Helpers
// ---------------------------------------------------------------------------
__device__ __forceinline__ uint32_t packh2(float x, float y) {
    __half2 h = __floats2half2_rn(x, y);
    return *reinterpret_cast<uint32_t*>(&h);
}

__device__ __forceinline__ void mma16816(float4& d,
        uint32_t a0, uint32_t a1, uint32_t a2, uint32_t a3,
        uint32_t b0, uint32_t b1) {
    asm volatile("mma.sync.aligned.m16n8k16.row.col.f32.f16.f16.f32 "
        "{%0,%1,%2,%3}, {%4,%5,%6,%7}, {%8,%9}, {%0,%1,%2,%3};"
        : "+f"(d.x), "+f"(d.y), "+f"(d.z), "+f"(d.w)
        : "r"(a0), "r"(a1), "r"(a2), "r"(a3), "r"(b0), "r"(b1));
}

__device__ __forceinline__ void ldsm4(uint32_t& r0, uint32_t& r1,
                                      uint32_t& r2, uint32_t& r3, uint32_t addr) {
    asm volatile("ldmatrix.sync.aligned.m8n8.x4.shared.b16 {%0,%1,%2,%3}, [%4];"
        : "=r"(r0), "=r"(r1), "=r"(r2), "=r"(r3) : "r"(addr));
}

__device__ __forceinline__ void red2(float* p, float x, float y) {
    asm volatile("red.global.add.v2.f32 [%0], {%1, %2};" :: "l"(p), "f"(x), "f"(y) : "memory");
}

__device__ __forceinline__ uint32_t smem_u32(const void* p) {
    uint32_t a;
    asm("{ .reg .u64 t; cvta.to.shared.u64 t, %1; cvt.u32.u64 %0, t; }" : "=r"(a) : "l"(p));
    return a;
}

__device__ __forceinline__ void cpa16(uint32_t dst, const void* src) {
    asm volatile("cp.async.cg.shared.global [%0], [%1], 16;" :: "r"(dst), "l"(src) : "memory");
}
#define CP_COMMIT() asm volatile("cp.async.commit_group;" ::: "memory")

// ---------------------------------------------------------------------------
// K0: init winner grid to -1, out to 0, zero A pad rows
// ---------------------------------------------------------------------------
__global__ void init_kernel(float4* __restrict__ out) {
    int i = blockIdx.x * 256 + threadIdx.x;
    if (i < NV*Uc/4)    out[i] = make_float4(0.f, 0.f, 0.f, 0.f);
    if (i < NV*SLOTS/4) ((int4*)g_winner)[i] = make_int4(-1, -1, -1, -1);
    if (i < 3*2048) {   // pad rows Ec..EP of each type, 32 rows x 64 words
        int tt = i >> 11;
        int w  = i & 2047;
        g_Ah[((size_t)tt*EP + Ec)*64 + w] = 0;
    }
}

// ---------------------------------------------------------------------------
// K1: fdot[bv] = features[bv]·W_att[0:128] + b_att
// ---------------------------------------------------------------------------
__global__ void fdot_kernel(const float* __restrict__ feat,
                            const float* __restrict__ Wa,
                            const float* __restrict__ ba) {
    int w = (blockIdx.x * blockDim.x + threadIdx.x) >> 5;
    int lane = threadIdx.x & 31;
    if (w >= NV) return;
    const float4 f = ((const float4*)(feat + (size_t)w * Fc))[lane];
    const float4 a = __ldg(((const float4*)Wa) + lane);
    float s = f.x*a.x + f.y*a.y + f.z*a.z + f.w*a.w;
#pragma unroll
    for (int o = 16; o; o >>= 1) s += __shfl_xor_sync(0xffffffffu, s, o);
    if (lane == 0) g_fdot[w] = s + ba[0];
}

// ---------------------------------------------------------------------------
// K1b: w̃, cterm, and W^T fp16 pair image (unpadded)
// ---------------------------------------------------------------------------
__global__ void prep_kernel(const float* __restrict__ Wd,
                            const float* __restrict__ bd,
                            const float* __restrict__ Wa) {
    int t = blockIdx.x;
    int tid = threadIdx.x;   // 256
    if (tid < 128) {
        const float* row = Wd + ((size_t)t * 128 + tid) * 128;
        float s = 0.f;
#pragma unroll 8
        for (int u = 0; u < 128; u++) s += row[u] * __ldg(&Wa[128 + u]);
        g_wtilde[t * 128 + tid] = s;
        if (tid == 0) {
            float cb = 0.f;
            for (int u = 0; u < 128; u++) cb += bd[t * 128 + u] * Wa[128 + u];
            g_cterm[t] = cb;
        }
    }
    for (int i = tid; i < 128 * 64; i += 256) {
        int n  = i >> 6;       // output col (N dim)
        int kp = i & 63;       // k pair
        float w0 = Wd[(size_t)t * 16384 + (size_t)(2*kp)     * 128 + n];
        float w1 = Wd[(size_t)t * 16384 + (size_t)(2*kp + 1) * 128 + n];
        g_Wh[(size_t)t * 8192 + n * 64 + kp] = packh2(w0, w1);
    }
}

// ---------------------------------------------------------------------------
// K2: logits (4 edges/warp) + fp16 A emission (row-major, EP stride)
// ---------------------------------------------------------------------------
__global__ void logits_kernel(const float* __restrict__ ef,
                              const int*   __restrict__ eidx) {
    int wg = (blockIdx.x * 256 + threadIdx.x) >> 5;
    int lane = threadIdx.x & 31;
    if (wg >= Tc * (Ec/4)) return;
    int t = wg / (Ec/4);
    int e0 = (wg - t * (Ec/4)) * 4;
    const float4* base = (const float4*)(ef + ((size_t)t * Ec + e0) * 128);
    float4 a0 = base[lane];
    float4 a1 = base[32 + lane];
    float4 a2 = base[64 + lane];
    float4 a3 = base[96 + lane];
    const float4 w = __ldg(((const float4*)(g_wtilde + t * 128)) + lane);
    float s0 = a0.x*w.x + a0.y*w.y + a0.z*w.z + a0.w*w.w;
    float s1 = a1.x*w.x + a1.y*w.y + a1.z*w.z + a1.w*w.w;
    float s2 = a2.x*w.x + a2.y*w.y + a2.z*w.z + a2.w*w.w;
    float s3 = a3.x*w.x + a3.y*w.y + a3.z*w.z + a3.w*w.w;

    // emit fp16 A, 64 words per row, EP stride
    {
        float4 rows[4] = {a0, a1, a2, a3};
#pragma unroll
        for (int j = 0; j < 4; j++) {
            size_t off = ((size_t)t*EP + e0 + j)*64 + 2*lane;
            *(uint2*)&g_Ah[off] = make_uint2(packh2(rows[j].x, rows[j].y),
                                             packh2(rows[j].z, rows[j].w));
        }
    }

#pragma unroll
    for (int o = 16; o; o >>= 1) {
        s0 += __shfl_xor_sync(0xffffffffu, s0, o);
        s1 += __shfl_xor_sync(0xffffffffu, s1, o);
        s2 += __shfl_xor_sync(0xffffffffu, s2, o);
        s3 += __shfl_xor_sync(0xffffffffu, s3, o);
    }
    if (lane < 4) {
        float sv = (lane == 0) ? s0 : (lane == 1) ? s1 : (lane == 2) ? s2 : s3;
        int e = e0 + lane;
        const int* ei = eidx + ((size_t)t * Ec + e) * 3;
        int b = ei[0], v = ei[1], sl = ei[2];
        int bv = b * Vc + v;
        float x = g_fdot[bv] + sv + g_cterm[t];
        float logit = (x > 0.0f) ? x : 0.3f * x;
        g_logits[t * Ec + e] = logit;
        atomicMax(&g_winner[bv * SLOTS + t * Nc + sl], e);
    }
}

// ---------------------------------------------------------------------------
// K3: per-vertex softmax stats
// ---------------------------------------------------------------------------
__global__ void vertex_kernel(const int* __restrict__ adj) {
    int vert = (blockIdx.x * blockDim.x + threadIdx.x) >> 5;
    int lane = threadIdx.x & 31;
    if (vert >= NV) return;
    const int base = vert * SLOTS;
    float l[3];
    int deg = 0;
#pragma unroll
    for (int i = 0; i < 3; i++) {
        int slot = i * 32 + lane;
        int w = g_winner[base + slot];
        deg += (adj[base + slot] >= 0) ? 1 : 0;
        l[i] = (w >= 0) ? g_logits[i * Ec + w] : -200.0f;
    }
    float m = fmaxf(fmaxf(l[0], l[1]), l[2]);
#pragma unroll
    for (int o = 16; o; o >>= 1) m = fmaxf(m, __shfl_xor_sync(0xffffffffu, m, o));
    float den = expf(l[0] - m) + expf(l[1] - m) + expf(l[2] - m);
#pragma unroll
    for (int o = 16; o; o >>= 1) {
        den += __shfl_xor_sync(0xffffffffu, den, o);
        deg += __shfl_xor_sync(0xffffffffu, deg, o);
    }
    if (lane == 0) { g_m[vert] = m; g_c[vert] = (float)deg / den; }
}

// ---------------------------------------------------------------------------
// K4: fp16 1-MMA GEMM (A single, W single), cp.async pipeline, fused scatter.
// SMEM (bytes): W [0,32768) xor-swizzled (g' = g^(n&7));
//   A: 3 bufs x 8192 at 32768, g' = g ^ ((row>>1)&3); satt/sbv after buffers.
// ---------------------------------------------------------------------------
#define W_OFF 0
#define ABUF_OFF 32768
#define SATT_OFF (ABUF_OFF + 3*8192)
#define SBV_OFF  (SATT_OFF + 512)
#define SMEM_BYTES (SBV_OFF + 512)   // 58880

__global__ __launch_bounds__(256, 2)
void gemm_hmma(const float* __restrict__ bd,    // [T,128]
               const int*   __restrict__ eidx,  // [T,E,3]
               float* __restrict__ out)
{
    extern __shared__ uint32_t sm[];
    char* smc = (char*)sm;
    const int tid  = threadIdx.x;
    const int lane = tid & 31;
    const int wid  = tid >> 5;
    const int wm   = wid >> 2;          // 0..1 : row-block of 64
    const int wn   = wid & 3;           // 0..3 : col-block of 32
    const int gi   = lane >> 2;         // 0..7
    const int m4   = lane >> 3;         // ldmatrix matrix idx
    const int lr   = lane & 7;
    const int t    = blockIdx.y;

    // --- prologue: W into smem with xor swizzle; bias into regs
    {
        const uint4* gw = (const uint4*)(g_Wh + (size_t)t*8192);
        uint4* sw = (uint4*)(smc + W_OFF);
        for (int idx = tid; idx < 2048; idx += 256) {
            int n = idx >> 4, g = idx & 15;
            int d = n*16 + (g ^ (n & 7));
            sw[d] = gw[idx];
        }
    }
    float biasr[8];
#pragma unroll
    for (int nf = 0; nf < 4; nf++) {
        biasr[nf*2]   = bd[t*128 + wn*32 + nf*8 + (lane&3)*2];
        biasr[nf*2+1] = bd[t*128 + wn*32 + nf*8 + (lane&3)*2 + 1];
    }
    __syncthreads();

    float* satt = (float*)(smc + SATT_OFF);
    int*   sbv  = (int*)(smc + SBV_OFF);
    const uint32_t smb = smem_u32(sm);

    // ldmatrix per-lane constants
    const uint32_t wbase  = smb + W_OFF + (uint32_t)(wn*32 + (m4>>1)*8 + lr) * 256;
    const uint32_t gbitB  = (uint32_t)(m4 & 1);
    const uint32_t abase0 = smb + ABUF_OFF + (uint32_t)(wm*64 + (m4&1)*8 + lr) * 64;
    const uint32_t ga2    = (uint32_t)(m4 >> 1);
    const uint32_t sA     = (uint32_t)((lr >> 1) & 3);

    // cp.async per-thread indices: 2 granules per chunk
    const int rcp = tid >> 1;                 // 0..127
    const int gcp = (tid & 1) * 2;            // 0 or 2
    const uint32_t sAcp = (uint32_t)((rcp >> 1) & 3);

    for (int tile = blockIdx.x; tile < NT; tile += GRIDX) {
        const int e0 = tile * 128;
        const int rowsv = min(128, Ec - e0);

        // --- att prefetch (long-latency chain overlapped with whole tile)
        float attR = 0.f; int bvR = 0;
        if (tid < 128 && tid < rowsv) {
            int e = e0 + tid;
            const int* ei = eidx + ((size_t)t * Ec + e) * 3;
            int b = ei[0], v = ei[1], sl = ei[2];
            int bv = b * Vc + v;
            int w = g_winner[bv * SLOTS + t * Nc + sl];
            attR = expf(g_logits[t * Ec + w] - g_m[bv]) * g_c[bv];
            bvR = bv;
        }

        const char* srcA = (const char*)g_Ah + ((size_t)t*EP + e0 + rcp)*256;
        const uint32_t dstBase = smb + ABUF_OFF + (uint32_t)rcp*64;

        #define COPY_A(c) do { \
            uint32_t _dst = dstBase + (uint32_t)(((c)%3)*8192); \
            const char* _s = srcA + (c)*64; \
            _Pragma("unroll") \
            for (int q = 0; q < 2; q++) { \
                int _g = gcp + q; \
                uint32_t _sw = (uint32_t)((_g ^ sAcp) << 4); \
                cpa16(_dst + _sw, _s + _g*16); \
            } \
            CP_COMMIT(); \
        } while (0)

        float4 acc[4][4];
#pragma unroll
        for (int i = 0; i < 4; i++)
#pragma unroll
            for (int j = 0; j < 4; j++) acc[i][j] = make_float4(0.f,0.f,0.f,0.f);

        COPY_A(0);
        COPY_A(1);
        COPY_A(2);

        #define DO_CHUNK(c, WN, DOCOPY3) do { \
            asm volatile("cp.async.wait_group %0;" :: "n"(WN) : "memory"); \
            __syncthreads(); \
            const uint32_t abuf = abase0 + (uint32_t)(((c)%3)*8192); \
            _Pragma("unroll") \
            for (int kk = 0; kk < 2; kk++) { \
                uint32_t bA = wbase + ((((uint32_t)(c)*4u + (uint32_t)kk*2u + gbitB) ^ (uint32_t)lr) << 4); \
                uint32_t bh[8]; \
                ldsm4(bh[0],bh[1],bh[2],bh[3], bA); \
                ldsm4(bh[4],bh[5],bh[6],bh[7], bA + 4096); \
                uint32_t gsw = ((((uint32_t)kk*2u + ga2) ^ sA) << 4); \
                _Pragma("unroll") \
                for (int mf = 0; mf < 4; mf++) { \
                    uint32_t aaddr = abuf + (uint32_t)mf*1024 + gsw; \
                    uint32_t ah[4]; \
                    ldsm4(ah[0],ah[1],ah[2],ah[3], aaddr); \
                    _Pragma("unroll") \
                    for (int nf = 0; nf < 4; nf++) \
                        mma16816(acc[mf][nf], ah[0], ah[1], ah[2], ah[3], bh[2*nf], bh[2*nf+1]); \
                } \
            } \
            if (DOCOPY3) COPY_A(3); \
        } while (0)

        DO_CHUNK(0, 2, 0);
        DO_CHUNK(1, 1, 1);   // copy(3) here: all warps past sync(1) => MMA(0) done
        DO_CHUNK(2, 1, 0);
        DO_CHUNK(3, 0, 0);

        // --- epilogue: publish att/bv, then RED
        if (tid < 128) { satt[tid] = attR; sbv[tid] = bvR; }
        __syncthreads();

#pragma unroll
        for (int mf = 0; mf < 4; mf++) {
            int r0 = wm*64 + mf*16 + gi;
            int r1 = r0 + 8;
            float a0 = satt[r0], a1 = satt[r1];
            size_t o0 = (size_t)sbv[r0] * 128, o1 = (size_t)sbv[r1] * 128;
#pragma unroll
            for (int nf = 0; nf < 4; nf++) {
                int col = wn*32 + nf*8 + (lane & 3)*2;
                float4 ac = acc[mf][nf];
                red2(out + o0 + col, (ac.x + biasr[nf*2]) * a0, (ac.y + biasr[nf*2+1]) * a0);
                red2(out + o1 + col, (ac.z + biasr[nf*2]) * a1, (ac.w + biasr[nf*2+1]) * a1);
            }
        }
        __syncthreads();   // protects satt/sbv + buffers before next tile's copies
        #undef DO_CHUNK
        #undef COPY_A
    }
}

// ---------------------------------------------------------------------------
extern "C" void kernel_launch(void* const* d_in, const int* in_sizes, int n_in,
                              void* d_out, int out_size) {
    const int*   adjacency  = (const int*)  d_in[0];
    const float* features   = (const float*)d_in[1];
    const int*   edge_idxs  = (const int*)  d_in[2];
    const float* edge_feats = (const float*)d_in[3];
    const float* W_dense    = (const float*)d_in[4];
    const float* b_dense    = (const float*)d_in[5];
    const float* W_att      = (const float*)d_in[6];
    const float* b_att      = (const float*)d_in[7];
    float* out = (float*)d_out;

    cudaFuncSetAttribute(gemm_hmma,
                         cudaFuncAttributeMaxDynamicSharedMemorySize, SMEM_BYTES);

    init_kernel<<<(NV*Uc/4 + 255)/256, 256>>>((float4*)out);
    fdot_kernel<<<(NV*32 + 255)/256, 256>>>(features, W_att, b_att);
    prep_kernel<<<Tc, 256>>>(W_dense, b_dense, W_att);
    logits_kernel<<<(Tc*(Ec/4)*32 + 255)/256, 256>>>(edge_feats, edge_idxs);
    vertex_kernel<<<(NV*32 + 255)/256, 256>>>(adjacency);
    dim3 gg(GRIDX, 3);
    gemm_hmma<<<gg, 256, SMEM_BYTES>>>(b_dense, edge_idxs, out);
}

// round 17
// speedup vs baseline: 2.3345x; 1.0115x over previous
#include <cuda_runtime.h>
#include <cuda_fp16.h>
#include <math.h>
#include <stdint.h>

// Problem constants (fixed by setup_inputs)
#define Bc 2
#define Vc 50000
#define Tc 3
#define Nc 32
#define Fc 128
#define Uc 128
#define Ec 300000
#define NV (Bc*Vc)          // 100000 vertices
#define SLOTS (Tc*Nc)       // 96 slots per vertex
#define NT ((Ec + 127) / 128)   // 2344 tiles per type
#define EP (NT*128)             // 300032 padded edge stride
#define GRIDX 296

// ---------------------------------------------------------------------------
// Device scratch (no allocation allowed)
// ---------------------------------------------------------------------------
__device__ float    g_logits[Tc*Ec];
__device__ int      g_winner[NV*SLOTS];
__device__ float    g_m[NV];
__device__ float    g_c[NV];
__device__ float    g_fdot[NV];
__device__ float    g_wtilde[Tc*Fc];       // W_t @ W_att[128:]
__device__ float    g_cterm[Tc];           // b_t · W_att[128:]
__device__ uint32_t g_Wh[Tc*128*64];       // W^T fp16-pairs, [n][kpair]
__device__ uint32_t g_Ah[(size_t)Tc*EP*64];// ef fp16-pairs, row-major

// ---------------------------------------------------------------------------
// Helpers
// ---------------------------------------------------------------------------
__device__ __forceinline__ uint32_t packh2(float x, float y) {
    __half2 h = __floats2half2_rn(x, y);
    return *reinterpret_cast<uint32_t*>(&h);
}

__device__ __forceinline__ void mma16816(float4& d,
        uint32_t a0, uint32_t a1, uint32_t a2, uint32_t a3,
        uint32_t b0, uint32_t b1) {
    asm volatile("mma.sync.aligned.m16n8k16.row.col.f32.f16.f16.f32 "
        "{%0,%1,%2,%3}, {%4,%5,%6,%7}, {%8,%9}, {%0,%1,%2,%3};"
        : "+f"(d.x), "+f"(d.y), "+f"(d.z), "+f"(d.w)
        : "r"(a0), "r"(a1), "r"(a2), "r"(a3), "r"(b0), "r"(b1));
}

__device__ __forceinline__ void ldsm4(uint32_t& r0, uint32_t& r1,
                                      uint32_t& r2, uint32_t& r3, uint32_t addr) {
    asm volatile("ldmatrix.sync.aligned.m8n8.x4.shared.b16 {%0,%1,%2,%3}, [%4];"
        : "=r"(r0), "=r"(r1), "=r"(r2), "=r"(r3) : "r"(addr));
}

__device__ __forceinline__ void red2(float* p, float x, float y) {
    asm volatile("red.global.add.v2.f32 [%0], {%1, %2};" :: "l"(p), "f"(x), "f"(y) : "memory");
}

__device__ __forceinline__ uint32_t smem_u32(const void* p) {
    uint32_t a;
    asm("{ .reg .u64 t; cvta.to.shared.u64 t, %1; cvt.u32.u64 %0, t; }" : "=r"(a) : "l"(p));
    return a;
}

__device__ __forceinline__ void cpa16(uint32_t dst, const void* src) {
    asm volatile("cp.async.cg.shared.global [%0], [%1], 16;" :: "r"(dst), "l"(src) : "memory");
}
#define CP_COMMIT() asm volatile("cp.async.commit_group;" ::: "memory")

// ---------------------------------------------------------------------------
// K0: init winner grid to -1, out to 0, zero A pad rows
// ---------------------------------------------------------------------------
__global__ void init_kernel(float4* __restrict__ out) {
    int i = blockIdx.x * 256 + threadIdx.x;
    if (i < NV*Uc/4)    out[i] = make_float4(0.f, 0.f, 0.f, 0.f);
    if (i < NV*SLOTS/4) ((int4*)g_winner)[i] = make_int4(-1, -1, -1, -1);
    if (i < 3*2048) {   // pad rows Ec..EP of each type, 32 rows x 64 words
        int tt = i >> 11;
        int w  = i & 2047;
        g_Ah[((size_t)tt*EP + Ec)*64 + w] = 0;
    }
}

// ---------------------------------------------------------------------------
// K1: fdot[bv] = features[bv]·W_att[0:128] + b_att
// ---------------------------------------------------------------------------
__global__ void fdot_kernel(const float* __restrict__ feat,
                            const float* __restrict__ Wa,
                            const float* __restrict__ ba) {
    int w = (blockIdx.x * blockDim.x + threadIdx.x) >> 5;
    int lane = threadIdx.x & 31;
    if (w >= NV) return;
    const float4 f = ((const float4*)(feat + (size_t)w * Fc))[lane];
    const float4 a = __ldg(((const float4*)Wa) + lane);
    float s = f.x*a.x + f.y*a.y + f.z*a.z + f.w*a.w;
#pragma unroll
    for (int o = 16; o; o >>= 1) s += __shfl_xor_sync(0xffffffffu, s, o);
    if (lane == 0) g_fdot[w] = s + ba[0];
}

// ---------------------------------------------------------------------------
// K1b: w̃, cterm, and W^T fp16 pair image (unpadded)
// ---------------------------------------------------------------------------
__global__ void prep_kernel(const float* __restrict__ Wd,
                            const float* __restrict__ bd,
                            const float* __restrict__ Wa) {
    int t = blockIdx.x;
    int tid = threadIdx.x;   // 256
    if (tid < 128) {
        const float* row = Wd + ((size_t)t * 128 + tid) * 128;
        float s = 0.f;
#pragma unroll 8
        for (int u = 0; u < 128; u++) s += row[u] * __ldg(&Wa[128 + u]);
        g_wtilde[t * 128 + tid] = s;
        if (tid == 0) {
            float cb = 0.f;
            for (int u = 0; u < 128; u++) cb += bd[t * 128 + u] * Wa[128 + u];
            g_cterm[t] = cb;
        }
    }
    for (int i = tid; i < 128 * 64; i += 256) {
        int n  = i >> 6;       // output col (N dim)
        int kp = i & 63;       // k pair
        float w0 = Wd[(size_t)t * 16384 + (size_t)(2*kp)     * 128 + n];
        float w1 = Wd[(size_t)t * 16384 + (size_t)(2*kp + 1) * 128 + n];
        g_Wh[(size_t)t * 8192 + n * 64 + kp] = packh2(w0, w1);
    }
}

// ---------------------------------------------------------------------------
// K2: logits (4 edges/warp) + fp16 A emission (row-major, EP stride)
// ---------------------------------------------------------------------------
__global__ void logits_kernel(const float* __restrict__ ef,
                              const int*   __restrict__ eidx) {
    int wg = (blockIdx.x * 256 + threadIdx.x) >> 5;
    int lane = threadIdx.x & 31;
    if (wg >= Tc * (Ec/4)) return;
    int t = wg / (Ec/4);
    int e0 = (wg - t * (Ec/4)) * 4;
    const float4* base = (const float4*)(ef + ((size_t)t * Ec + e0) * 128);
    float4 a0 = base[lane];
    float4 a1 = base[32 + lane];
    float4 a2 = base[64 + lane];
    float4 a3 = base[96 + lane];
    const float4 w = __ldg(((const float4*)(g_wtilde + t * 128)) + lane);
    float s0 = a0.x*w.x + a0.y*w.y + a0.z*w.z + a0.w*w.w;
    float s1 = a1.x*w.x + a1.y*w.y + a1.z*w.z + a1.w*w.w;
    float s2 = a2.x*w.x + a2.y*w.y + a2.z*w.z + a2.w*w.w;
    float s3 = a3.x*w.x + a3.y*w.y + a3.z*w.z + a3.w*w.w;

    // emit fp16 A, 64 words per row, EP stride
    {
        float4 rows[4] = {a0, a1, a2, a3};
#pragma unroll
        for (int j = 0; j < 4; j++) {
            size_t off = ((size_t)t*EP + e0 + j)*64 + 2*lane;
            *(uint2*)&g_Ah[off] = make_uint2(packh2(rows[j].x, rows[j].y),
                                             packh2(rows[j].z, rows[j].w));
        }
    }

#pragma unroll
    for (int o = 16; o; o >>= 1) {
        s0 += __shfl_xor_sync(0xffffffffu, s0, o);
        s1 += __shfl_xor_sync(0xffffffffu, s1, o);
        s2 += __shfl_xor_sync(0xffffffffu, s2, o);
        s3 += __shfl_xor_sync(0xffffffffu, s3, o);
    }
    if (lane < 4) {
        float sv = (lane == 0) ? s0 : (lane == 1) ? s1 : (lane == 2) ? s2 : s3;
        int e = e0 + lane;
        const int* ei = eidx + ((size_t)t * Ec + e) * 3;
        int b = ei[0], v = ei[1], sl = ei[2];
        int bv = b * Vc + v;
        float x = g_fdot[bv] + sv + g_cterm[t];
        float logit = (x > 0.0f) ? x : 0.3f * x;
        g_logits[t * Ec + e] = logit;
        atomicMax(&g_winner[bv * SLOTS + t * Nc + sl], e);
    }
}

// ---------------------------------------------------------------------------
// K3: per-vertex softmax stats
// ---------------------------------------------------------------------------
__global__ void vertex_kernel(const int* __restrict__ adj) {
    int vert = (blockIdx.x * blockDim.x + threadIdx.x) >> 5;
    int lane = threadIdx.x & 31;
    if (vert >= NV) return;
    const int base = vert * SLOTS;
    float l[3];
    int deg = 0;
#pragma unroll
    for (int i = 0; i < 3; i++) {
        int slot = i * 32 + lane;
        int w = g_winner[base + slot];
        deg += (adj[base + slot] >= 0) ? 1 : 0;
        l[i] = (w >= 0) ? g_logits[i * Ec + w] : -200.0f;
    }
    float m = fmaxf(fmaxf(l[0], l[1]), l[2]);
#pragma unroll
    for (int o = 16; o; o >>= 1) m = fmaxf(m, __shfl_xor_sync(0xffffffffu, m, o));
    float den = expf(l[0] - m) + expf(l[1] - m) + expf(l[2] - m);
#pragma unroll
    for (int o = 16; o; o >>= 1) {
        den += __shfl_xor_sync(0xffffffffu, den, o);
        deg += __shfl_xor_sync(0xffffffffu, deg, o);
    }
    if (lane == 0) { g_m[vert] = m; g_c[vert] = (float)deg / den; }
}

// ---------------------------------------------------------------------------
// K4: fp16 1-MMA GEMM with CONTINUOUS cross-tile cp.async pipeline.
// Per chunk: wait_group(1) -> sync -> issue copy(q+2) -> MMA(q).
// copy(q+2) targets buffer (q-1)%3 whose MMA is complete for all warps
// past the sync. Tiles' epilogue REDs overlap next tile's copies.
// SMEM (bytes): W [0,32768) xor-swizzled (g' = g^(n&7));
//   A: 3 bufs x 8192 at 32768, g' = g ^ ((row>>1)&3); satt/sbv after buffers.
// ---------------------------------------------------------------------------
#define W_OFF 0
#define ABUF_OFF 32768
#define SATT_OFF (ABUF_OFF + 3*8192)
#define SBV_OFF  (SATT_OFF + 512)
#define SMEM_BYTES (SBV_OFF + 512)   // 58880

__global__ __launch_bounds__(256, 2)
void gemm_hmma(const float* __restrict__ bd,    // [T,128]
               const int*   __restrict__ eidx,  // [T,E,3]
               float* __restrict__ out)
{
    extern __shared__ uint32_t sm[];
    char* smc = (char*)sm;
    const int tid  = threadIdx.x;
    const int lane = tid & 31;
    const int wid  = tid >> 5;
    const int wm   = wid >> 2;          // 0..1 : row-block of 64
    const int wn   = wid & 3;           // 0..3 : col-block of 32
    const int gi   = lane >> 2;         // 0..7
    const int m4   = lane >> 3;         // ldmatrix matrix idx
    const int lr   = lane & 7;
    const int t    = blockIdx.y;
    const int bx   = blockIdx.x;

    // --- prologue: W into smem with xor swizzle; bias into regs
    {
        const uint4* gw = (const uint4*)(g_Wh + (size_t)t*8192);
        uint4* sw = (uint4*)(smc + W_OFF);
        for (int idx = tid; idx < 2048; idx += 256) {
            int n = idx >> 4, g = idx & 15;
            int d = n*16 + (g ^ (n & 7));
            sw[d] = gw[idx];
        }
    }
    float biasr[8];
#pragma unroll
    for (int nf = 0; nf < 4; nf++) {
        biasr[nf*2]   = bd[t*128 + wn*32 + nf*8 + (lane&3)*2];
        biasr[nf*2+1] = bd[t*128 + wn*32 + nf*8 + (lane&3)*2 + 1];
    }
    __syncthreads();

    float* satt = (float*)(smc + SATT_OFF);
    int*   sbv  = (int*)(smc + SBV_OFF);
    const uint32_t smb = smem_u32(sm);

    // ldmatrix per-lane constants
    const uint32_t wbase  = smb + W_OFF + (uint32_t)(wn*32 + (m4>>1)*8 + lr) * 256;
    const uint32_t gbitB  = (uint32_t)(m4 & 1);
    const uint32_t abase0 = smb + ABUF_OFF + (uint32_t)(wm*64 + (m4&1)*8 + lr) * 64;
    const uint32_t ga2    = (uint32_t)(m4 >> 1);
    const uint32_t sA     = (uint32_t)((lr >> 1) & 3);

    // cp.async per-thread indices: 2 granules per chunk
    const int rcp = tid >> 1;                 // 0..127
    const int gcp = (tid & 1) * 2;            // 0 or 2
    const uint32_t sAcp = (uint32_t)((rcp >> 1) & 3);

    const int ntiles  = (NT - bx + GRIDX - 1) / GRIDX;
    const int nchunks = ntiles * 4;
    const char* srcBase = (const char*)g_Ah + ((size_t)t*EP + rcp)*256;
    const uint32_t dstT = smb + ABUF_OFF + (uint32_t)rcp*64;

    // issue copy for global chunk q into buffer bufp (0..2); ALWAYS commit
    #define ISSUE_COPY(q, bufp) do { \
        if ((q) < nchunks) { \
            int _ti = (q) >> 2, _c = (q) & 3; \
            const char* _s = srcBase + ((size_t)(bx + _ti*GRIDX) * 128) * 256 + (size_t)(_c * 64); \
            uint32_t _dst = dstT + (uint32_t)((bufp)*8192); \
            _Pragma("unroll") \
            for (int _qq = 0; _qq < 2; _qq++) { \
                int _g = gcp + _qq; \
                cpa16(_dst + ((uint32_t)(_g ^ sAcp) << 4), _s + _g*16); \
            } \
        } \
        CP_COMMIT(); \
    } while (0)

    int qp = 0, bufp = 0;    // producer cursor
    int bufc = 0;            // consumer buffer
    ISSUE_COPY(qp, bufp); qp++; bufp = 1;
    ISSUE_COPY(qp, bufp); qp++; bufp = 2;

    for (int tile = bx; tile < NT; tile += GRIDX) {
        const int e0 = tile * 128;
        const int rowsv = min(128, Ec - e0);

        // --- att prefetch (long-latency chain overlapped with whole tile)
        float attR = 0.f; int bvR = 0;
        if (tid < 128 && tid < rowsv) {
            int e = e0 + tid;
            const int* ei = eidx + ((size_t)t * Ec + e) * 3;
            int b = ei[0], v = ei[1], sl = ei[2];
            int bv = b * Vc + v;
            int w = g_winner[bv * SLOTS + t * Nc + sl];
            attR = expf(g_logits[t * Ec + w] - g_m[bv]) * g_c[bv];
            bvR = bv;
        }

        float4 acc[4][4];
#pragma unroll
        for (int i = 0; i < 4; i++)
#pragma unroll
            for (int j = 0; j < 4; j++) acc[i][j] = make_float4(0.f,0.f,0.f,0.f);

#pragma unroll
        for (int c = 0; c < 4; c++) {
            asm volatile("cp.async.wait_group 1;" ::: "memory");
            __syncthreads();
            ISSUE_COPY(qp, bufp);
            qp++; bufp = (bufp == 2) ? 0 : bufp + 1;

            const uint32_t abuf = abase0 + (uint32_t)(bufc*8192);
            bufc = (bufc == 2) ? 0 : bufc + 1;
#pragma unroll
            for (int kk = 0; kk < 2; kk++) {
                uint32_t bA = wbase + ((((uint32_t)c*4u + (uint32_t)kk*2u + gbitB) ^ (uint32_t)lr) << 4);
                uint32_t bh[8];
                ldsm4(bh[0],bh[1],bh[2],bh[3], bA);
                ldsm4(bh[4],bh[5],bh[6],bh[7], bA + 4096);
                uint32_t gsw = ((((uint32_t)kk*2u + ga2) ^ sA) << 4);
#pragma unroll
                for (int mf = 0; mf < 4; mf++) {
                    uint32_t aaddr = abuf + (uint32_t)mf*1024 + gsw;
                    uint32_t ah[4];
                    ldsm4(ah[0],ah[1],ah[2],ah[3], aaddr);
#pragma unroll
                    for (int nf = 0; nf < 4; nf++)
                        mma16816(acc[mf][nf], ah[0], ah[1], ah[2], ah[3], bh[2*nf], bh[2*nf+1]);
                }
            }
        }

        // --- epilogue: publish att/bv, one sync, REDs (overlap next tile's copies)
        if (tid < 128) { satt[tid] = attR; sbv[tid] = bvR; }
        __syncthreads();

#pragma unroll
        for (int mf = 0; mf < 4; mf++) {
            int r0 = wm*64 + mf*16 + gi;
            int r1 = r0 + 8;
            float a0 = satt[r0], a1 = satt[r1];
            size_t o0 = (size_t)sbv[r0] * 128, o1 = (size_t)sbv[r1] * 128;
#pragma unroll
            for (int nf = 0; nf < 4; nf++) {
                int col = wn*32 + nf*8 + (lane & 3)*2;
                float4 ac = acc[mf][nf];
                red2(out + o0 + col, (ac.x + biasr[nf*2]) * a0, (ac.y + biasr[nf*2+1]) * a0);
                red2(out + o1 + col, (ac.z + biasr[nf*2]) * a1, (ac.w + biasr[nf*2+1]) * a1);
            }
        }
        // no trailing sync needed: satt/sbv next overwritten only after 4 chunk
        // syncs of the next tile; A buffers protected by the chunk-sync invariant.
    }
    #undef ISSUE_COPY
}

// ---------------------------------------------------------------------------
extern "C" void kernel_launch(void* const* d_in, const int* in_sizes, int n_in,
                              void* d_out, int out_size) {
    const int*   adjacency  = (const int*)  d_in[0];
    const float* features   = (const float*)d_in[1];
    const int*   edge_idxs  = (const int*)  d_in[2];
    const float* edge_feats = (const float*)d_in[3];
    const float* W_dense    = (const float*)d_in[4];
    const float* b_dense    = (const float*)d_in[5];
    const float* W_att      = (const float*)d_in[6];
    const float* b_att      = (const float*)d_in[7];
    float* out = (float*)d_out;

    cudaFuncSetAttribute(gemm_hmma,
                         cudaFuncAttributeMaxDynamicSharedMemorySize, SMEM_BYTES);

    init_kernel<<<(NV*Uc/4 + 255)/256, 256>>>((float4*)out);
    fdot_kernel<<<(NV*32 + 255)/256, 256>>>(features, W_att, b_att);
    prep_kernel<<<Tc, 256>>>(W_dense, b_dense, W_att);
    logits_kernel<<<(Tc*(Ec/4)*32 + 255)/256, 256>>>(edge_feats, edge_idxs);
    vertex_kernel<<<(NV*32 + 255)/256, 256>>>(adjacency);
    dim3 gg(GRIDX, 3);
    gemm_hmma<<<gg, 256, SMEM_BYTES>>>(b_dense, edge_idxs, out);
}